// round 2
// baseline (speedup 1.0000x reference)
#include <cuda_runtime.h>
#include <math.h>
#include <stdint.h>
#include <stddef.h>

#define BB   4
#define SS   2048
#define DD   1024
#define HH   16
#define HDIM 64
#define DFFN 4096
#define MTOT (BB*SS)   // 8192

// ---------------- scratch (no allocations allowed) ----------------
__device__ float g_q  [(size_t)MTOT*DD];
__device__ float g_k  [(size_t)MTOT*DD];
__device__ float g_v  [(size_t)MTOT*DD];
__device__ float g_ctx[(size_t)MTOT*DD];
__device__ float g_t1 [(size_t)MTOT*DD];
__device__ float g_att[(size_t)MTOT*DD];
__device__ float g_h  [(size_t)MTOT*DFFN];
__device__ float g_t2 [(size_t)MTOT*DD];

// ---------------- tiled SGEMM: C = A[M,K] @ B[K,N] + bias (+res) (+gelu) ----
// EPI: 0 = bias only, 1 = bias + residual, 2 = bias + exact gelu
template<int EPI>
__global__ __launch_bounds__(256)
void gemm_kernel(const float* __restrict__ A, const float* __restrict__ Bm,
                 const float* __restrict__ bias, const float* __restrict__ res,
                 float* __restrict__ C, int M, int N, int K)
{
    __shared__ float As[16][128];
    __shared__ float Bs[16][128];

    const int bm = blockIdx.y * 128;
    const int bn = blockIdx.x * 128;
    const int tid = threadIdx.x;
    const int ty = tid >> 4;       // 0..15
    const int tx = tid & 15;       // 0..15

    float acc[8][8];
    #pragma unroll
    for (int i = 0; i < 8; i++)
        #pragma unroll
        for (int j = 0; j < 8; j++) acc[i][j] = 0.f;

    for (int k0 = 0; k0 < K; k0 += 16) {
        #pragma unroll
        for (int i = 0; i < 2; i++) {
            int id = tid + i * 256;            // 0..511 (float4 units)
            // A tile: 128 rows x 16 cols -> transpose into As[k][m]
            int ar = id >> 2, ac4 = id & 3;
            float4 a = *(const float4*)(A + (size_t)(bm + ar) * K + k0 + ac4 * 4);
            As[ac4*4+0][ar] = a.x; As[ac4*4+1][ar] = a.y;
            As[ac4*4+2][ar] = a.z; As[ac4*4+3][ar] = a.w;
            // B tile: 16 rows x 128 cols -> direct
            int br = id >> 5, bc4 = id & 31;
            *(float4*)(&Bs[br][bc4*4]) =
                *(const float4*)(Bm + (size_t)(k0 + br) * N + bn + bc4 * 4);
        }
        __syncthreads();

        #pragma unroll
        for (int kk = 0; kk < 16; kk++) {
            float af[8], bf[8];
            #pragma unroll
            for (int i = 0; i < 8; i++) af[i] = As[kk][ty*8 + i];
            #pragma unroll
            for (int j = 0; j < 8; j++) bf[j] = Bs[kk][tx*8 + j];
            #pragma unroll
            for (int i = 0; i < 8; i++)
                #pragma unroll
                for (int j = 0; j < 8; j++)
                    acc[i][j] += af[i] * bf[j];
        }
        __syncthreads();
    }

    // epilogue
    float4 b0 = *(const float4*)(bias + bn + tx*8);
    float4 b1 = *(const float4*)(bias + bn + tx*8 + 4);
    #pragma unroll
    for (int i = 0; i < 8; i++) {
        int row = bm + ty*8 + i;
        float* crow = C + (size_t)row * N + bn + tx*8;
        float v[8];
        v[0]=acc[i][0]+b0.x; v[1]=acc[i][1]+b0.y; v[2]=acc[i][2]+b0.z; v[3]=acc[i][3]+b0.w;
        v[4]=acc[i][4]+b1.x; v[5]=acc[i][5]+b1.y; v[6]=acc[i][6]+b1.z; v[7]=acc[i][7]+b1.w;
        if (EPI == 1) {
            const float* rrow = res + (size_t)row * N + bn + tx*8;
            float4 r0 = *(const float4*)(rrow);
            float4 r1 = *(const float4*)(rrow + 4);
            v[0]+=r0.x; v[1]+=r0.y; v[2]+=r0.z; v[3]+=r0.w;
            v[4]+=r1.x; v[5]+=r1.y; v[6]+=r1.z; v[7]+=r1.w;
        }
        if (EPI == 2) {
            #pragma unroll
            for (int j = 0; j < 8; j++)
                v[j] = 0.5f * v[j] * (1.0f + erff(v[j] * 0.70710678118654752f));
        }
        float4 o0 = make_float4(v[0],v[1],v[2],v[3]);
        float4 o1 = make_float4(v[4],v[5],v[6],v[7]);
        *(float4*)(crow)     = o0;
        *(float4*)(crow + 4) = o1;
    }
}

// ---------------- flash attention (fp32), 64q x 64k tiles ----------------
__global__ __launch_bounds__(256)
void attn_kernel(const float* __restrict__ Q, const float* __restrict__ K,
                 const float* __restrict__ V, const float* __restrict__ mask,
                 float* __restrict__ O)
{
    extern __shared__ float smem[];
    float (*Qs)[64] = (float(*)[64])(smem);             // [r][d]
    float (*Kt)[64] = (float(*)[64])(smem + 4096);      // [d][j] (transposed)
    float (*Vs)[64] = (float(*)[64])(smem + 8192);      // [j][d]
    float (*Ps)[64] = (float(*)[64])(smem + 12288);     // [r][j]
    float  *Ms      = smem + 16384;                     // [64]

    const int bh = blockIdx.y;
    const int b  = bh / HH;
    const int h  = bh % HH;
    const int q0 = blockIdx.x * 64;
    const int tid = threadIdx.x;
    const int ty = tid >> 4;   // 0..15 -> query rows ty*4..ty*4+3
    const int tx = tid & 15;   // 0..15 -> cols tx*4..tx*4+3

    const float* Qbase = Q + (size_t)b * SS * DD + (size_t)h * HDIM;
    const float* Kbase = K + (size_t)b * SS * DD + (size_t)h * HDIM;
    const float* Vbase = V + (size_t)b * SS * DD + (size_t)h * HDIM;

    // load Q tile (64 x 64)
    #pragma unroll
    for (int i = 0; i < 4; i++) {
        int id = tid + i * 256;          // float4 units, 0..1023
        int r = id >> 4, c4 = id & 15;
        *(float4*)&Qs[r][c4*4] =
            *(const float4*)(Qbase + (size_t)(q0 + r) * DD + c4 * 4);
    }

    float m[4], l[4], o[4][4];
    #pragma unroll
    for (int i = 0; i < 4; i++) {
        m[i] = -INFINITY; l[i] = 0.f;
        #pragma unroll
        for (int j = 0; j < 4; j++) o[i][j] = 0.f;
    }

    for (int kt = 0; kt < SS; kt += 64) {
        // load K (transposed) + V tiles
        #pragma unroll
        for (int i = 0; i < 4; i++) {
            int id = tid + i * 256;
            int r = id >> 4, c4 = id & 15;
            float4 kv = *(const float4*)(Kbase + (size_t)(kt + r) * DD + c4 * 4);
            Kt[c4*4+0][r] = kv.x; Kt[c4*4+1][r] = kv.y;
            Kt[c4*4+2][r] = kv.z; Kt[c4*4+3][r] = kv.w;
            *(float4*)&Vs[r][c4*4] =
                *(const float4*)(Vbase + (size_t)(kt + r) * DD + c4 * 4);
        }
        if (tid < 64) Ms[tid] = mask[(size_t)b * SS + kt + tid];
        __syncthreads();

        // scores: s[i][j] = sum_d Qs[qr+i][d] * Kt[d][kc+j]
        float s[4][4];
        #pragma unroll
        for (int i = 0; i < 4; i++)
            #pragma unroll
            for (int j = 0; j < 4; j++) s[i][j] = 0.f;
        #pragma unroll 4
        for (int d = 0; d < 64; d++) {
            float qf[4], kf[4];
            #pragma unroll
            for (int i = 0; i < 4; i++) qf[i] = Qs[ty*4 + i][d];
            #pragma unroll
            for (int j = 0; j < 4; j++) kf[j] = Kt[d][tx*4 + j];
            #pragma unroll
            for (int i = 0; i < 4; i++)
                #pragma unroll
                for (int j = 0; j < 4; j++)
                    s[i][j] += qf[i] * kf[j];
        }
        #pragma unroll
        for (int i = 0; i < 4; i++)
            #pragma unroll
            for (int j = 0; j < 4; j++)
                s[i][j] = s[i][j] * 0.125f + Ms[tx*4 + j];

        // online softmax
        float mn[4], corr[4], ls[4];
        #pragma unroll
        for (int i = 0; i < 4; i++) {
            float tmax = fmaxf(fmaxf(s[i][0], s[i][1]), fmaxf(s[i][2], s[i][3]));
            #pragma unroll
            for (int w = 1; w < 16; w <<= 1)
                tmax = fmaxf(tmax, __shfl_xor_sync(0xffffffffu, tmax, w, 16));
            mn[i]   = fmaxf(m[i], tmax);
            corr[i] = expf(m[i] - mn[i]);
            float sum = 0.f;
            #pragma unroll
            for (int j = 0; j < 4; j++) {
                float p = expf(s[i][j] - mn[i]);
                s[i][j] = p;
                sum += p;
            }
            #pragma unroll
            for (int w = 1; w < 16; w <<= 1)
                sum += __shfl_xor_sync(0xffffffffu, sum, w, 16);
            ls[i] = sum;
            l[i] = l[i] * corr[i] + ls[i];
            m[i] = mn[i];
            #pragma unroll
            for (int j = 0; j < 4; j++) o[i][j] *= corr[i];
        }

        // stage P
        #pragma unroll
        for (int i = 0; i < 4; i++)
            #pragma unroll
            for (int j = 0; j < 4; j++)
                Ps[ty*4 + i][tx*4 + j] = s[i][j];
        __syncthreads();

        // o += P @ V
        #pragma unroll 4
        for (int j = 0; j < 64; j++) {
            float pv[4], vv[4];
            #pragma unroll
            for (int i = 0; i < 4; i++) pv[i] = Ps[ty*4 + i][j];
            #pragma unroll
            for (int dj = 0; dj < 4; dj++) vv[dj] = Vs[j][tx*4 + dj];
            #pragma unroll
            for (int i = 0; i < 4; i++)
                #pragma unroll
                for (int dj = 0; dj < 4; dj++)
                    o[i][dj] += pv[i] * vv[dj];
        }
        __syncthreads();
    }

    // write ctx in [B,S,D] layout
    #pragma unroll
    for (int i = 0; i < 4; i++) {
        float inv = 1.0f / l[i];
        float4 ov = make_float4(o[i][0]*inv, o[i][1]*inv, o[i][2]*inv, o[i][3]*inv);
        size_t row = (size_t)b * SS + q0 + ty*4 + i;
        *(float4*)(O + row * DD + h * HDIM + tx * 4) = ov;
    }
}

// ---------------- LayerNorm over rows of DD ----------------
__global__ __launch_bounds__(256)
void ln_kernel(const float* __restrict__ X, const float* __restrict__ gw,
               const float* __restrict__ bw, float* __restrict__ Y)
{
    __shared__ float red[2][8];
    const int row = blockIdx.x;
    const int tid = threadIdx.x;
    const float* x = X + (size_t)row * DD;

    float4 v = *(const float4*)(x + tid * 4);
    float s  = v.x + v.y + v.z + v.w;
    float sq = v.x*v.x + v.y*v.y + v.z*v.z + v.w*v.w;
    #pragma unroll
    for (int w = 16; w > 0; w >>= 1) {
        s  += __shfl_xor_sync(0xffffffffu, s,  w);
        sq += __shfl_xor_sync(0xffffffffu, sq, w);
    }
    if ((tid & 31) == 0) { red[0][tid >> 5] = s; red[1][tid >> 5] = sq; }
    __syncthreads();
    float tot = 0.f, totq = 0.f;
    #pragma unroll
    for (int i = 0; i < 8; i++) { tot += red[0][i]; totq += red[1][i]; }

    float mean = tot * (1.0f / DD);
    float var  = totq * (1.0f / DD) - mean * mean;
    float inv  = rsqrtf(var + 1e-12f);

    float4 gg = *(const float4*)(gw + tid * 4);
    float4 bb = *(const float4*)(bw + tid * 4);
    float4 out;
    out.x = (v.x - mean) * inv * gg.x + bb.x;
    out.y = (v.y - mean) * inv * gg.y + bb.y;
    out.z = (v.z - mean) * inv * gg.z + bb.z;
    out.w = (v.w - mean) * inv * gg.w + bb.w;
    *(float4*)(Y + (size_t)row * DD + tid * 4) = out;
}

// ---------------- host launch ----------------
extern "C" void kernel_launch(void* const* d_in, const int* in_sizes, int n_in,
                              void* d_out, int out_size)
{
    const float* x    = (const float*)d_in[0];
    const float* mask = (const float*)d_in[1];
    const float* Wq   = (const float*)d_in[2];
    const float* bq   = (const float*)d_in[3];
    const float* Wk   = (const float*)d_in[4];
    const float* bk   = (const float*)d_in[5];
    const float* Wv   = (const float*)d_in[6];
    const float* bv   = (const float*)d_in[7];
    const float* Wo   = (const float*)d_in[8];
    const float* bo   = (const float*)d_in[9];
    const float* ln1g = (const float*)d_in[10];
    const float* ln1b = (const float*)d_in[11];
    const float* Wi   = (const float*)d_in[12];
    const float* bi   = (const float*)d_in[13];
    const float* Wo2  = (const float*)d_in[14];
    const float* bo2  = (const float*)d_in[15];
    const float* ln2g = (const float*)d_in[16];
    const float* ln2b = (const float*)d_in[17];

    float *q, *k, *v, *ctx, *t1, *att, *h, *t2;
    cudaGetSymbolAddress((void**)&q,   g_q);
    cudaGetSymbolAddress((void**)&k,   g_k);
    cudaGetSymbolAddress((void**)&v,   g_v);
    cudaGetSymbolAddress((void**)&ctx, g_ctx);
    cudaGetSymbolAddress((void**)&t1,  g_t1);
    cudaGetSymbolAddress((void**)&att, g_att);
    cudaGetSymbolAddress((void**)&h,   g_h);
    cudaGetSymbolAddress((void**)&t2,  g_t2);

    const int ATTN_SMEM = (4 * 4096 + 64) * (int)sizeof(float);
    cudaFuncSetAttribute(attn_kernel, cudaFuncAttributeMaxDynamicSharedMemorySize, ATTN_SMEM);

    dim3 gD(DD / 128, MTOT / 128);       // 8 x 64
    dim3 gF(DFFN / 128, MTOT / 128);     // 32 x 64

    // QKV projections
    gemm_kernel<0><<<gD, 256>>>(x, Wq, bq, nullptr, q, MTOT, DD, DD);
    gemm_kernel<0><<<gD, 256>>>(x, Wk, bk, nullptr, k, MTOT, DD, DD);
    gemm_kernel<0><<<gD, 256>>>(x, Wv, bv, nullptr, v, MTOT, DD, DD);

    // attention
    attn_kernel<<<dim3(SS / 64, BB * HH), 256, ATTN_SMEM>>>(q, k, v, mask, ctx);

    // O projection + residual, then LN1
    gemm_kernel<1><<<gD, 256>>>(ctx, Wo, bo, x, t1, MTOT, DD, DD);
    ln_kernel<<<MTOT, 256>>>(t1, ln1g, ln1b, att);

    // FFN
    gemm_kernel<2><<<gF, 256>>>(att, Wi, bi, nullptr, h, MTOT, DFFN, DD);
    gemm_kernel<1><<<gD, 256>>>(h, Wo2, bo2, att, t2, MTOT, DD, DFFN);
    ln_kernel<<<MTOT, 256>>>(t2, ln2g, ln2b, (float*)d_out);
}

// round 4
// speedup vs baseline: 1.6227x; 1.6227x over previous
#include <cuda_runtime.h>
#include <cuda_bf16.h>
#include <math.h>
#include <stdint.h>
#include <stddef.h>

#define BB   4
#define SS   2048
#define DD   1024
#define HH   16
#define HDIM 64
#define DFFN 4096
#define MTOT (BB*SS)   // 8192

// ======================= scratch =======================
__device__ float g_q  [(size_t)MTOT*DD];
__device__ float g_k  [(size_t)MTOT*DD];
__device__ float g_v  [(size_t)MTOT*DD];
__device__ float g_ctx[(size_t)MTOT*DD];
__device__ float g_t1 [(size_t)MTOT*DD];
__device__ float g_att[(size_t)MTOT*DD];
__device__ float g_t2 [(size_t)MTOT*DD];
__device__ __nv_bfloat16 g_xh [(size_t)MTOT*DD];
__device__ __nv_bfloat16 g_xl [(size_t)MTOT*DD];
__device__ __nv_bfloat16 g_cth[(size_t)MTOT*DD];
__device__ __nv_bfloat16 g_ctl[(size_t)MTOT*DD];
__device__ __nv_bfloat16 g_ath[(size_t)MTOT*DD];
__device__ __nv_bfloat16 g_atl[(size_t)MTOT*DD];
__device__ __nv_bfloat16 g_hh [(size_t)MTOT*DFFN];
__device__ __nv_bfloat16 g_hl [(size_t)MTOT*DFFN];
// transposed-decomposed weights [N, K]
__device__ __nv_bfloat16 g_wqh[(size_t)DD*DD],  g_wql[(size_t)DD*DD];
__device__ __nv_bfloat16 g_wkh[(size_t)DD*DD],  g_wkl[(size_t)DD*DD];
__device__ __nv_bfloat16 g_wvh[(size_t)DD*DD],  g_wvl[(size_t)DD*DD];
__device__ __nv_bfloat16 g_woh[(size_t)DD*DD],  g_wol[(size_t)DD*DD];
__device__ __nv_bfloat16 g_wih[(size_t)DD*DFFN], g_wil[(size_t)DD*DFFN];
__device__ __nv_bfloat16 g_w2h[(size_t)DFFN*DD], g_w2l[(size_t)DFFN*DD];

// ======================= helpers =======================
__device__ __forceinline__ uint32_t smem_u32(const void* p) {
    uint32_t a;
    asm("{ .reg .u64 t; cvta.to.shared.u64 t, %1; cvt.u32.u64 %0, t; }" : "=r"(a) : "l"(p));
    return a;
}
__device__ __forceinline__ uint32_t pack_bf2(float a, float b) {
    __nv_bfloat162 t = __floats2bfloat162_rn(a, b);
    return *reinterpret_cast<uint32_t*>(&t);
}
__device__ __forceinline__ void split1(float v, float& hi, float& lo) {
    __nv_bfloat16 h = __float2bfloat16_rn(v);
    hi = __bfloat162float(h);
    lo = v - hi;
}

#define CP_ASYNC16(dst, src) \
    asm volatile("cp.async.cg.shared.global [%0], [%1], 16;" :: "r"(dst), "l"(src) : "memory")
#define CP_COMMIT() asm volatile("cp.async.commit_group;" ::: "memory")
#define CP_WAIT1()  asm volatile("cp.async.wait_group 1;" ::: "memory")

#define LDSM_X4(r0, r1, r2, r3, addr) \
    asm volatile("ldmatrix.sync.aligned.m8n8.x4.shared.b16 {%0,%1,%2,%3}, [%4];" \
        : "=r"(r0), "=r"(r1), "=r"(r2), "=r"(r3) : "r"(addr))

#define MMA_BF16(d, a, b) \
    asm volatile("mma.sync.aligned.m16n8k16.row.col.f32.bf16.bf16.f32 " \
        "{%0,%1,%2,%3}, {%4,%5,%6,%7}, {%8,%9}, {%0,%1,%2,%3};" \
        : "+f"((d)[0]), "+f"((d)[1]), "+f"((d)[2]), "+f"((d)[3]) \
        : "r"((a)[0]), "r"((a)[1]), "r"((a)[2]), "r"((a)[3]), \
          "r"((b)[0]), "r"((b)[1]))

// decompose fp32 -> bf16 hi/lo
__global__ __launch_bounds__(256)
void decomp_kernel(const float4* __restrict__ in, uint2* __restrict__ oh,
                   uint2* __restrict__ ol, int n4)
{
    int i = blockIdx.x * 256 + threadIdx.x;
    if (i >= n4) return;
    float4 v = in[i];
    float hx,lx,hy,ly,hz,lz,hw,lw;
    split1(v.x,hx,lx); split1(v.y,hy,ly); split1(v.z,hz,lz); split1(v.w,hw,lw);
    oh[i] = make_uint2(pack_bf2(hx,hy), pack_bf2(hz,hw));
    ol[i] = make_uint2(pack_bf2(lx,ly), pack_bf2(lz,lw));
}

// transpose + decompose: W [K,N] fp32 -> Th/Tl [N,K] bf16
__global__ __launch_bounds__(256)
void wtrans_kernel(const float* __restrict__ W, __nv_bfloat16* __restrict__ Th,
                   __nv_bfloat16* __restrict__ Tl, int K, int N)
{
    __shared__ float tile[32][33];
    int n0 = blockIdx.x * 32, k0 = blockIdx.y * 32;
    int tx = threadIdx.x & 31, ty = threadIdx.x >> 5; // 32 x 8
    #pragma unroll
    for (int i = ty; i < 32; i += 8)
        tile[i][tx] = W[(size_t)(k0 + i) * N + n0 + tx];
    __syncthreads();
    #pragma unroll
    for (int i = ty; i < 32; i += 8) {
        float v = tile[tx][i];
        float h, l; split1(v, h, l);
        size_t o = (size_t)(n0 + i) * K + k0 + tx;
        Th[o] = __float2bfloat16_rn(h);
        Tl[o] = __float2bfloat16_rn(l);
    }
}

// ======================= mma.sync split-bf16 GEMM =======================
// C[M,N] = A[M,K] @ B^T (B stored [N,K]); A,B as bf16 hi/lo pairs.
// EPI 0: +bias -> fp32 ; EPI 1: +bias+res -> fp32 ; EPI 2: +bias,gelu -> bf16 hi/lo
// SMEM per stage: Ah@0, Al@10240, Bh@20480, Bl@30720; row stride 80B (32 bf16 + pad)
#define STG_BYTES 40960

template<int EPI>
__global__ __launch_bounds__(256)
void mma_gemm(const __nv_bfloat16* __restrict__ Ah, const __nv_bfloat16* __restrict__ Al,
              const __nv_bfloat16* __restrict__ Bh, const __nv_bfloat16* __restrict__ Bl,
              const float* __restrict__ bias, const float* __restrict__ res,
              float* __restrict__ outF, __nv_bfloat16* __restrict__ outH,
              __nv_bfloat16* __restrict__ outL, int M, int N, int K)
{
    extern __shared__ char dsm[];
    const int tid = threadIdx.x;
    const int wid = tid >> 5;
    const int lane = tid & 31;
    const int bm = blockIdx.y * 128;
    const int bn = blockIdx.x * 128;
    const int warpM = (wid & 1) * 64;
    const int warpN = (wid >> 1) * 32;
    const uint32_t sbase = smem_u32(dsm);

    float acc[4][4][4];
    #pragma unroll
    for (int mt = 0; mt < 4; mt++)
        #pragma unroll
        for (int nt = 0; nt < 4; nt++)
            #pragma unroll
            for (int r = 0; r < 4; r++) acc[mt][nt][r] = 0.f;

    const int NC = K >> 5;   // BK = 32

    // prefetch stage 0
    {
        #pragma unroll
        for (int t = 0; t < 2; t++) {
            int id = tid + t * 256;
            int row = id >> 2, ch = id & 3;
            uint32_t doff = sbase + row * 80 + ch * 16;
            size_t ga = (size_t)(bm + row) * K + ch * 8;
            size_t gb = (size_t)(bn + row) * K + ch * 8;
            CP_ASYNC16(doff,          Ah + ga);
            CP_ASYNC16(doff + 10240,  Al + ga);
            CP_ASYNC16(doff + 20480,  Bh + gb);
            CP_ASYNC16(doff + 30720,  Bl + gb);
        }
        CP_COMMIT();
    }

    for (int c = 0; c < NC; c++) {
        const int s = c & 1;
        if (c + 1 < NC) {
            const int k0 = (c + 1) << 5;
            uint32_t sb2 = sbase + (s ^ 1) * STG_BYTES;
            #pragma unroll
            for (int t = 0; t < 2; t++) {
                int id = tid + t * 256;
                int row = id >> 2, ch = id & 3;
                uint32_t doff = sb2 + row * 80 + ch * 16;
                size_t ga = (size_t)(bm + row) * K + k0 + ch * 8;
                size_t gb = (size_t)(bn + row) * K + k0 + ch * 8;
                CP_ASYNC16(doff,          Ah + ga);
                CP_ASYNC16(doff + 10240,  Al + ga);
                CP_ASYNC16(doff + 20480,  Bh + gb);
                CP_ASYNC16(doff + 30720,  Bl + gb);
            }
        }
        CP_COMMIT();
        CP_WAIT1();
        __syncthreads();

        const uint32_t sb = sbase + s * STG_BYTES;
        const uint32_t arow = (lane & 15);
        const uint32_t khalf = (lane >> 4);
        #pragma unroll
        for (int ks = 0; ks < 2; ks++) {
            uint32_t ah[4][4], al[4][4], bh[4][2], bl[4][2];
            const uint32_t koff = ks * 32 + khalf * 16;
            #pragma unroll
            for (int mt = 0; mt < 4; mt++) {
                uint32_t ra = sb + (warpM + mt * 16 + arow) * 80 + koff;
                LDSM_X4(ah[mt][0], ah[mt][1], ah[mt][2], ah[mt][3], ra);
                LDSM_X4(al[mt][0], al[mt][1], al[mt][2], al[mt][3], ra + 10240);
            }
            #pragma unroll
            for (int g = 0; g < 2; g++) {
                uint32_t rb = sb + 20480 + (warpN + g * 16 + arow) * 80 + koff;
                uint32_t r0, r1, r2, r3;
                LDSM_X4(r0, r1, r2, r3, rb);
                bh[g*2+0][0] = r0; bh[g*2+0][1] = r2;
                bh[g*2+1][0] = r1; bh[g*2+1][1] = r3;
                LDSM_X4(r0, r1, r2, r3, rb + 10240);
                bl[g*2+0][0] = r0; bl[g*2+0][1] = r2;
                bl[g*2+1][0] = r1; bl[g*2+1][1] = r3;
            }
            #pragma unroll
            for (int mt = 0; mt < 4; mt++)
                #pragma unroll
                for (int nt = 0; nt < 4; nt++) {
                    MMA_BF16(acc[mt][nt], ah[mt], bh[nt]);
                    MMA_BF16(acc[mt][nt], ah[mt], bl[nt]);
                    MMA_BF16(acc[mt][nt], al[mt], bh[nt]);
                }
        }
        __syncthreads();
    }

    // ---- epilogue ----
    #pragma unroll
    for (int mt = 0; mt < 4; mt++) {
        #pragma unroll
        for (int nt = 0; nt < 4; nt++) {
            const int row0 = bm + warpM + mt * 16 + (lane >> 2);
            const int col  = bn + warpN + nt * 8 + (lane & 3) * 2;
            float2 bb = *(const float2*)(bias + col);
            float v0 = acc[mt][nt][0] + bb.x;
            float v1 = acc[mt][nt][1] + bb.y;
            float v2 = acc[mt][nt][2] + bb.x;
            float v3 = acc[mt][nt][3] + bb.y;
            if (EPI == 1) {
                float2 r0 = *(const float2*)(res + (size_t)row0 * N + col);
                float2 r1 = *(const float2*)(res + (size_t)(row0 + 8) * N + col);
                v0 += r0.x; v1 += r0.y; v2 += r1.x; v3 += r1.y;
            }
            if (EPI <= 1) {
                *(float2*)(outF + (size_t)row0 * N + col)       = make_float2(v0, v1);
                *(float2*)(outF + (size_t)(row0 + 8) * N + col) = make_float2(v2, v3);
            }
            if (EPI == 2) {
                v0 = 0.5f * v0 * (1.0f + erff(v0 * 0.70710678118654752f));
                v1 = 0.5f * v1 * (1.0f + erff(v1 * 0.70710678118654752f));
                v2 = 0.5f * v2 * (1.0f + erff(v2 * 0.70710678118654752f));
                v3 = 0.5f * v3 * (1.0f + erff(v3 * 0.70710678118654752f));
                float h0,l0,h1,l1,h2,l2,h3,l3;
                split1(v0,h0,l0); split1(v1,h1,l1);
                split1(v2,h2,l2); split1(v3,h3,l3);
                *(uint32_t*)(outH + (size_t)row0 * N + col)       = pack_bf2(h0, h1);
                *(uint32_t*)(outL + (size_t)row0 * N + col)       = pack_bf2(l0, l1);
                *(uint32_t*)(outH + (size_t)(row0 + 8) * N + col) = pack_bf2(h2, h3);
                *(uint32_t*)(outL + (size_t)(row0 + 8) * N + col) = pack_bf2(l2, l3);
            }
        }
    }
}

// ======================= flash attention (fp32) =======================
__global__ __launch_bounds__(256)
void attn_kernel(const float* __restrict__ Q, const float* __restrict__ K,
                 const float* __restrict__ V, const float* __restrict__ mask,
                 float* __restrict__ O)
{
    extern __shared__ float smemf[];
    float (*Qs)[64] = (float(*)[64])(smemf);
    float (*Kt)[64] = (float(*)[64])(smemf + 4096);
    float (*Vs)[64] = (float(*)[64])(smemf + 8192);
    float (*Ps)[64] = (float(*)[64])(smemf + 12288);
    float  *Ms      = smemf + 16384;

    const int bh = blockIdx.y;
    const int b  = bh / HH;
    const int h  = bh % HH;
    const int q0 = blockIdx.x * 64;
    const int tid = threadIdx.x;
    const int ty = tid >> 4;
    const int tx = tid & 15;

    const float* Qbase = Q + (size_t)b * SS * DD + (size_t)h * HDIM;
    const float* Kbase = K + (size_t)b * SS * DD + (size_t)h * HDIM;
    const float* Vbase = V + (size_t)b * SS * DD + (size_t)h * HDIM;

    #pragma unroll
    for (int i = 0; i < 4; i++) {
        int id = tid + i * 256;
        int r = id >> 4, c4 = id & 15;
        *(float4*)&Qs[r][c4*4] =
            *(const float4*)(Qbase + (size_t)(q0 + r) * DD + c4 * 4);
    }

    float m[4], l[4], o[4][4];
    #pragma unroll
    for (int i = 0; i < 4; i++) {
        m[i] = -INFINITY; l[i] = 0.f;
        #pragma unroll
        for (int j = 0; j < 4; j++) o[i][j] = 0.f;
    }

    for (int kt = 0; kt < SS; kt += 64) {
        #pragma unroll
        for (int i = 0; i < 4; i++) {
            int id = tid + i * 256;
            int r = id >> 4, c4 = id & 15;
            float4 kv = *(const float4*)(Kbase + (size_t)(kt + r) * DD + c4 * 4);
            Kt[c4*4+0][r] = kv.x; Kt[c4*4+1][r] = kv.y;
            Kt[c4*4+2][r] = kv.z; Kt[c4*4+3][r] = kv.w;
            *(float4*)&Vs[r][c4*4] =
                *(const float4*)(Vbase + (size_t)(kt + r) * DD + c4 * 4);
        }
        if (tid < 64) Ms[tid] = mask[(size_t)b * SS + kt + tid];
        __syncthreads();

        float s[4][4];
        #pragma unroll
        for (int i = 0; i < 4; i++)
            #pragma unroll
            for (int j = 0; j < 4; j++) s[i][j] = 0.f;
        #pragma unroll 4
        for (int d = 0; d < 64; d++) {
            float qf[4], kf[4];
            #pragma unroll
            for (int i = 0; i < 4; i++) qf[i] = Qs[ty*4 + i][d];
            #pragma unroll
            for (int j = 0; j < 4; j++) kf[j] = Kt[d][tx*4 + j];
            #pragma unroll
            for (int i = 0; i < 4; i++)
                #pragma unroll
                for (int j = 0; j < 4; j++)
                    s[i][j] += qf[i] * kf[j];
        }
        #pragma unroll
        for (int i = 0; i < 4; i++)
            #pragma unroll
            for (int j = 0; j < 4; j++)
                s[i][j] = s[i][j] * 0.125f + Ms[tx*4 + j];

        #pragma unroll
        for (int i = 0; i < 4; i++) {
            float tmax = fmaxf(fmaxf(s[i][0], s[i][1]), fmaxf(s[i][2], s[i][3]));
            #pragma unroll
            for (int w = 1; w < 16; w <<= 1)
                tmax = fmaxf(tmax, __shfl_xor_sync(0xffffffffu, tmax, w, 16));
            float mn   = fmaxf(m[i], tmax);
            float corr = expf(m[i] - mn);
            float sum = 0.f;
            #pragma unroll
            for (int j = 0; j < 4; j++) {
                float p = expf(s[i][j] - mn);
                s[i][j] = p;
                sum += p;
            }
            #pragma unroll
            for (int w = 1; w < 16; w <<= 1)
                sum += __shfl_xor_sync(0xffffffffu, sum, w, 16);
            l[i] = l[i] * corr + sum;
            m[i] = mn;
            #pragma unroll
            for (int j = 0; j < 4; j++) o[i][j] *= corr;
        }

        #pragma unroll
        for (int i = 0; i < 4; i++)
            #pragma unroll
            for (int j = 0; j < 4; j++)
                Ps[ty*4 + i][tx*4 + j] = s[i][j];
        __syncthreads();

        #pragma unroll 4
        for (int j = 0; j < 64; j++) {
            float pv[4], vv[4];
            #pragma unroll
            for (int i = 0; i < 4; i++) pv[i] = Ps[ty*4 + i][j];
            #pragma unroll
            for (int dj = 0; dj < 4; dj++) vv[dj] = Vs[j][tx*4 + dj];
            #pragma unroll
            for (int i = 0; i < 4; i++)
                #pragma unroll
                for (int dj = 0; dj < 4; dj++)
                    o[i][dj] += pv[i] * vv[dj];
        }
        __syncthreads();
    }

    #pragma unroll
    for (int i = 0; i < 4; i++) {
        float inv = 1.0f / l[i];
        float4 ov = make_float4(o[i][0]*inv, o[i][1]*inv, o[i][2]*inv, o[i][3]*inv);
        size_t row = (size_t)b * SS + q0 + ty*4 + i;
        *(float4*)(O + row * DD + h * HDIM + tx * 4) = ov;
    }
}

// ======================= LayerNorm =======================
template<bool EMIT>
__global__ __launch_bounds__(256)
void ln_kernel(const float* __restrict__ X, const float* __restrict__ gw,
               const float* __restrict__ bw, float* __restrict__ Y,
               __nv_bfloat16* __restrict__ Yh, __nv_bfloat16* __restrict__ Yl)
{
    __shared__ float red[2][8];
    const int row = blockIdx.x;
    const int tid = threadIdx.x;
    const float* x = X + (size_t)row * DD;

    float4 v = *(const float4*)(x + tid * 4);
    float s  = v.x + v.y + v.z + v.w;
    float sq = v.x*v.x + v.y*v.y + v.z*v.z + v.w*v.w;
    #pragma unroll
    for (int w = 16; w > 0; w >>= 1) {
        s  += __shfl_xor_sync(0xffffffffu, s,  w);
        sq += __shfl_xor_sync(0xffffffffu, sq, w);
    }
    if ((tid & 31) == 0) { red[0][tid >> 5] = s; red[1][tid >> 5] = sq; }
    __syncthreads();
    float tot = 0.f, totq = 0.f;
    #pragma unroll
    for (int i = 0; i < 8; i++) { tot += red[0][i]; totq += red[1][i]; }

    float mean = tot * (1.0f / DD);
    float var  = totq * (1.0f / DD) - mean * mean;
    float inv  = rsqrtf(var + 1e-12f);

    float4 gg = *(const float4*)(gw + tid * 4);
    float4 bb = *(const float4*)(bw + tid * 4);
    float4 out;
    out.x = (v.x - mean) * inv * gg.x + bb.x;
    out.y = (v.y - mean) * inv * gg.y + bb.y;
    out.z = (v.z - mean) * inv * gg.z + bb.z;
    out.w = (v.w - mean) * inv * gg.w + bb.w;
    *(float4*)(Y + (size_t)row * DD + tid * 4) = out;

    if (EMIT) {
        float hx,lx,hy,ly,hz,lz,hw,lw;
        split1(out.x,hx,lx); split1(out.y,hy,ly);
        split1(out.z,hz,lz); split1(out.w,hw,lw);
        size_t ob = (size_t)row * DD + tid * 4;
        *(uint2*)(Yh + ob) = make_uint2(pack_bf2(hx,hy), pack_bf2(hz,hw));
        *(uint2*)(Yl + ob) = make_uint2(pack_bf2(lx,ly), pack_bf2(lz,lw));
    }
}

// ======================= host launch =======================
extern "C" void kernel_launch(void* const* d_in, const int* in_sizes, int n_in,
                              void* d_out, int out_size)
{
    const float* x    = (const float*)d_in[0];
    const float* mask = (const float*)d_in[1];
    const float* Wq   = (const float*)d_in[2];
    const float* bq   = (const float*)d_in[3];
    const float* Wk   = (const float*)d_in[4];
    const float* bk   = (const float*)d_in[5];
    const float* Wv   = (const float*)d_in[6];
    const float* bv   = (const float*)d_in[7];
    const float* Wo   = (const float*)d_in[8];
    const float* bo   = (const float*)d_in[9];
    const float* ln1g = (const float*)d_in[10];
    const float* ln1b = (const float*)d_in[11];
    const float* Wi   = (const float*)d_in[12];
    const float* bi   = (const float*)d_in[13];
    const float* Wo2  = (const float*)d_in[14];
    const float* bo2  = (const float*)d_in[15];
    const float* ln2g = (const float*)d_in[16];
    const float* ln2b = (const float*)d_in[17];

    float *q, *k, *v, *ctx, *t1, *att, *t2;
    __nv_bfloat16 *xh, *xl, *cth, *ctl, *ath, *atl, *hh, *hl;
    __nv_bfloat16 *wqh,*wql,*wkh,*wkl,*wvh,*wvl,*woh,*wol,*wih,*wil,*w2h,*w2l;
    cudaGetSymbolAddress((void**)&q,   g_q);
    cudaGetSymbolAddress((void**)&k,   g_k);
    cudaGetSymbolAddress((void**)&v,   g_v);
    cudaGetSymbolAddress((void**)&ctx, g_ctx);
    cudaGetSymbolAddress((void**)&t1,  g_t1);
    cudaGetSymbolAddress((void**)&att, g_att);
    cudaGetSymbolAddress((void**)&t2,  g_t2);
    cudaGetSymbolAddress((void**)&xh,  g_xh);
    cudaGetSymbolAddress((void**)&xl,  g_xl);
    cudaGetSymbolAddress((void**)&cth, g_cth);
    cudaGetSymbolAddress((void**)&ctl, g_ctl);
    cudaGetSymbolAddress((void**)&ath, g_ath);
    cudaGetSymbolAddress((void**)&atl, g_atl);
    cudaGetSymbolAddress((void**)&hh,  g_hh);
    cudaGetSymbolAddress((void**)&hl,  g_hl);
    cudaGetSymbolAddress((void**)&wqh, g_wqh); cudaGetSymbolAddress((void**)&wql, g_wql);
    cudaGetSymbolAddress((void**)&wkh, g_wkh); cudaGetSymbolAddress((void**)&wkl, g_wkl);
    cudaGetSymbolAddress((void**)&wvh, g_wvh); cudaGetSymbolAddress((void**)&wvl, g_wvl);
    cudaGetSymbolAddress((void**)&woh, g_woh); cudaGetSymbolAddress((void**)&wol, g_wol);
    cudaGetSymbolAddress((void**)&wih, g_wih); cudaGetSymbolAddress((void**)&wil, g_wil);
    cudaGetSymbolAddress((void**)&w2h, g_w2h); cudaGetSymbolAddress((void**)&w2l, g_w2l);

    const int ATTN_SMEM = (4 * 4096 + 64) * (int)sizeof(float);
    cudaFuncSetAttribute(attn_kernel, cudaFuncAttributeMaxDynamicSharedMemorySize, ATTN_SMEM);
    const int GEMM_SMEM = 2 * STG_BYTES;   // 81920
    cudaFuncSetAttribute(mma_gemm<0>, cudaFuncAttributeMaxDynamicSharedMemorySize, GEMM_SMEM);
    cudaFuncSetAttribute(mma_gemm<1>, cudaFuncAttributeMaxDynamicSharedMemorySize, GEMM_SMEM);
    cudaFuncSetAttribute(mma_gemm<2>, cudaFuncAttributeMaxDynamicSharedMemorySize, GEMM_SMEM);

    // weight transforms (graph-captured, cheap)
    wtrans_kernel<<<dim3(DD/32, DD/32), 256>>>(Wq, wqh, wql, DD, DD);
    wtrans_kernel<<<dim3(DD/32, DD/32), 256>>>(Wk, wkh, wkl, DD, DD);
    wtrans_kernel<<<dim3(DD/32, DD/32), 256>>>(Wv, wvh, wvl, DD, DD);
    wtrans_kernel<<<dim3(DD/32, DD/32), 256>>>(Wo, woh, wol, DD, DD);
    wtrans_kernel<<<dim3(DFFN/32, DD/32), 256>>>(Wi, wih, wil, DD, DFFN);
    wtrans_kernel<<<dim3(DD/32, DFFN/32), 256>>>(Wo2, w2h, w2l, DFFN, DD);

    // decompose input
    decomp_kernel<<<(MTOT*DD/4 + 255)/256, 256>>>((const float4*)x, (uint2*)xh, (uint2*)xl, MTOT*DD/4);

    dim3 gQ(DD/128, MTOT/128);     // 8 x 64
    dim3 gF1(DFFN/128, MTOT/128);  // 32 x 64

    // QKV projections (tensor cores, split-bf16)
    mma_gemm<0><<<gQ, 256, GEMM_SMEM>>>(xh, xl, wqh, wql, bq, nullptr, q, nullptr, nullptr, MTOT, DD, DD);
    mma_gemm<0><<<gQ, 256, GEMM_SMEM>>>(xh, xl, wkh, wkl, bk, nullptr, k, nullptr, nullptr, MTOT, DD, DD);
    mma_gemm<0><<<gQ, 256, GEMM_SMEM>>>(xh, xl, wvh, wvl, bv, nullptr, v, nullptr, nullptr, MTOT, DD, DD);

    // attention (fp32)
    attn_kernel<<<dim3(SS/64, BB*HH), 256, ATTN_SMEM>>>(q, k, v, mask, ctx);

    // O projection + residual -> t1; LN1 -> att (+hi/lo)
    decomp_kernel<<<(MTOT*DD/4 + 255)/256, 256>>>((const float4*)ctx, (uint2*)cth, (uint2*)ctl, MTOT*DD/4);
    mma_gemm<1><<<gQ, 256, GEMM_SMEM>>>(cth, ctl, woh, wol, bo, x, t1, nullptr, nullptr, MTOT, DD, DD);
    ln_kernel<true><<<MTOT, 256>>>(t1, ln1g, ln1b, att, ath, atl);

    // FFN
    mma_gemm<2><<<gF1, 256, GEMM_SMEM>>>(ath, atl, wih, wil, bi, nullptr, nullptr, hh, hl, MTOT, DFFN, DD);
    mma_gemm<1><<<gQ, 256, GEMM_SMEM>>>(hh, hl, w2h, w2l, bo2, att, t2, nullptr, nullptr, MTOT, DD, DFFN);
    ln_kernel<false><<<MTOT, 256>>>(t2, ln2g, ln2b, (float*)d_out, nullptr, nullptr);
}

// round 5
// speedup vs baseline: 1.6272x; 1.0028x over previous
#include <cuda_runtime.h>
#include <cuda_bf16.h>
#include <math.h>
#include <stdint.h>
#include <stddef.h>

#define BB   4
#define SS   2048
#define DD   1024
#define HH   16
#define HDIM 64
#define DFFN 4096
#define MTOT (BB*SS)   // 8192

// ======================= scratch =======================
__device__ float g_t1 [(size_t)MTOT*DD];
__device__ float g_att[(size_t)MTOT*DD];
__device__ float g_t2 [(size_t)MTOT*DD];
__device__ __nv_bfloat16 g_xh [(size_t)MTOT*DD];
__device__ __nv_bfloat16 g_xl [(size_t)MTOT*DD];
__device__ __nv_bfloat16 g_qh [(size_t)MTOT*DD], g_ql [(size_t)MTOT*DD];
__device__ __nv_bfloat16 g_kh [(size_t)MTOT*DD], g_kl [(size_t)MTOT*DD];
__device__ __nv_bfloat16 g_vh [(size_t)MTOT*DD], g_vl [(size_t)MTOT*DD];
__device__ __nv_bfloat16 g_cth[(size_t)MTOT*DD], g_ctl[(size_t)MTOT*DD];
__device__ __nv_bfloat16 g_ath[(size_t)MTOT*DD], g_atl[(size_t)MTOT*DD];
__device__ __nv_bfloat16 g_hh [(size_t)MTOT*DFFN], g_hl [(size_t)MTOT*DFFN];
// transposed-decomposed weights [N, K]
__device__ __nv_bfloat16 g_wqh[(size_t)DD*DD],  g_wql[(size_t)DD*DD];
__device__ __nv_bfloat16 g_wkh[(size_t)DD*DD],  g_wkl[(size_t)DD*DD];
__device__ __nv_bfloat16 g_wvh[(size_t)DD*DD],  g_wvl[(size_t)DD*DD];
__device__ __nv_bfloat16 g_woh[(size_t)DD*DD],  g_wol[(size_t)DD*DD];
__device__ __nv_bfloat16 g_wih[(size_t)DD*DFFN], g_wil[(size_t)DD*DFFN];
__device__ __nv_bfloat16 g_w2h[(size_t)DFFN*DD], g_w2l[(size_t)DFFN*DD];

// ======================= helpers =======================
__device__ __forceinline__ uint32_t smem_u32(const void* p) {
    uint32_t a;
    asm("{ .reg .u64 t; cvta.to.shared.u64 t, %1; cvt.u32.u64 %0, t; }" : "=r"(a) : "l"(p));
    return a;
}
__device__ __forceinline__ uint32_t pack_bf2(float a, float b) {
    __nv_bfloat162 t = __floats2bfloat162_rn(a, b);
    return *reinterpret_cast<uint32_t*>(&t);
}
__device__ __forceinline__ void split1(float v, float& hi, float& lo) {
    __nv_bfloat16 h = __float2bfloat16_rn(v);
    hi = __bfloat162float(h);
    lo = v - hi;
}

#define CP_ASYNC16(dst, src) \
    asm volatile("cp.async.cg.shared.global [%0], [%1], 16;" :: "r"(dst), "l"(src) : "memory")
#define CP_COMMIT() asm volatile("cp.async.commit_group;" ::: "memory")
#define CP_WAIT1()  asm volatile("cp.async.wait_group 1;" ::: "memory")

#define LDSM_X4(r0, r1, r2, r3, addr) \
    asm volatile("ldmatrix.sync.aligned.m8n8.x4.shared.b16 {%0,%1,%2,%3}, [%4];" \
        : "=r"(r0), "=r"(r1), "=r"(r2), "=r"(r3) : "r"(addr))

#define LDSM_X4_T(r0, r1, r2, r3, addr) \
    asm volatile("ldmatrix.sync.aligned.m8n8.x4.trans.shared.b16 {%0,%1,%2,%3}, [%4];" \
        : "=r"(r0), "=r"(r1), "=r"(r2), "=r"(r3) : "r"(addr))

#define MMA_BF16(d, a, b) \
    asm volatile("mma.sync.aligned.m16n8k16.row.col.f32.bf16.bf16.f32 " \
        "{%0,%1,%2,%3}, {%4,%5,%6,%7}, {%8,%9}, {%0,%1,%2,%3};" \
        : "+f"((d)[0]), "+f"((d)[1]), "+f"((d)[2]), "+f"((d)[3]) \
        : "r"((a)[0]), "r"((a)[1]), "r"((a)[2]), "r"((a)[3]), \
          "r"((b)[0]), "r"((b)[1]))

// decompose fp32 -> bf16 hi/lo
__global__ __launch_bounds__(256)
void decomp_kernel(const float4* __restrict__ in, uint2* __restrict__ oh,
                   uint2* __restrict__ ol, int n4)
{
    int i = blockIdx.x * 256 + threadIdx.x;
    if (i >= n4) return;
    float4 v = in[i];
    float hx,lx,hy,ly,hz,lz,hw,lw;
    split1(v.x,hx,lx); split1(v.y,hy,ly); split1(v.z,hz,lz); split1(v.w,hw,lw);
    oh[i] = make_uint2(pack_bf2(hx,hy), pack_bf2(hz,hw));
    ol[i] = make_uint2(pack_bf2(lx,ly), pack_bf2(lz,lw));
}

// transpose + decompose: W [K,N] fp32 -> Th/Tl [N,K] bf16
__global__ __launch_bounds__(256)
void wtrans_kernel(const float* __restrict__ W, __nv_bfloat16* __restrict__ Th,
                   __nv_bfloat16* __restrict__ Tl, int K, int N)
{
    __shared__ float tile[32][33];
    int n0 = blockIdx.x * 32, k0 = blockIdx.y * 32;
    int tx = threadIdx.x & 31, ty = threadIdx.x >> 5; // 32 x 8
    #pragma unroll
    for (int i = ty; i < 32; i += 8)
        tile[i][tx] = W[(size_t)(k0 + i) * N + n0 + tx];
    __syncthreads();
    #pragma unroll
    for (int i = ty; i < 32; i += 8) {
        float v = tile[tx][i];
        float h, l; split1(v, h, l);
        size_t o = (size_t)(n0 + i) * K + k0 + tx;
        Th[o] = __float2bfloat16_rn(h);
        Tl[o] = __float2bfloat16_rn(l);
    }
}

// ======================= mma.sync split-bf16 GEMM =======================
// C[M,N] = A[M,K] @ B^T (B stored [N,K]); A,B as bf16 hi/lo pairs.
// EPI 0: +bias -> fp32 ; EPI 1: +bias+res -> fp32 ;
// EPI 2: +bias,gelu -> bf16 hi/lo ; EPI 3: (+bias)*scale -> bf16 hi/lo
#define STG_BYTES 40960

template<int EPI>
__global__ __launch_bounds__(256)
void mma_gemm(const __nv_bfloat16* __restrict__ Ah, const __nv_bfloat16* __restrict__ Al,
              const __nv_bfloat16* __restrict__ Bh, const __nv_bfloat16* __restrict__ Bl,
              const float* __restrict__ bias, const float* __restrict__ res,
              float* __restrict__ outF, __nv_bfloat16* __restrict__ outH,
              __nv_bfloat16* __restrict__ outL, int M, int N, int K, float oscale)
{
    extern __shared__ char dsm[];
    const int tid = threadIdx.x;
    const int wid = tid >> 5;
    const int lane = tid & 31;
    const int bm = blockIdx.y * 128;
    const int bn = blockIdx.x * 128;
    const int warpM = (wid & 1) * 64;
    const int warpN = (wid >> 1) * 32;
    const uint32_t sbase = smem_u32(dsm);

    float acc[4][4][4];
    #pragma unroll
    for (int mt = 0; mt < 4; mt++)
        #pragma unroll
        for (int nt = 0; nt < 4; nt++)
            #pragma unroll
            for (int r = 0; r < 4; r++) acc[mt][nt][r] = 0.f;

    const int NC = K >> 5;   // BK = 32

    {
        #pragma unroll
        for (int t = 0; t < 2; t++) {
            int id = tid + t * 256;
            int row = id >> 2, ch = id & 3;
            uint32_t doff = sbase + row * 80 + ch * 16;
            size_t ga = (size_t)(bm + row) * K + ch * 8;
            size_t gb = (size_t)(bn + row) * K + ch * 8;
            CP_ASYNC16(doff,          Ah + ga);
            CP_ASYNC16(doff + 10240,  Al + ga);
            CP_ASYNC16(doff + 20480,  Bh + gb);
            CP_ASYNC16(doff + 30720,  Bl + gb);
        }
        CP_COMMIT();
    }

    for (int c = 0; c < NC; c++) {
        const int s = c & 1;
        if (c + 1 < NC) {
            const int k0 = (c + 1) << 5;
            uint32_t sb2 = sbase + (s ^ 1) * STG_BYTES;
            #pragma unroll
            for (int t = 0; t < 2; t++) {
                int id = tid + t * 256;
                int row = id >> 2, ch = id & 3;
                uint32_t doff = sb2 + row * 80 + ch * 16;
                size_t ga = (size_t)(bm + row) * K + k0 + ch * 8;
                size_t gb = (size_t)(bn + row) * K + k0 + ch * 8;
                CP_ASYNC16(doff,          Ah + ga);
                CP_ASYNC16(doff + 10240,  Al + ga);
                CP_ASYNC16(doff + 20480,  Bh + gb);
                CP_ASYNC16(doff + 30720,  Bl + gb);
            }
        }
        CP_COMMIT();
        CP_WAIT1();
        __syncthreads();

        const uint32_t sb = sbase + s * STG_BYTES;
        const uint32_t arow = (lane & 15);
        const uint32_t khalf = (lane >> 4);
        #pragma unroll
        for (int ks = 0; ks < 2; ks++) {
            uint32_t ah[4][4], al[4][4], bh[4][2], bl[4][2];
            const uint32_t koff = ks * 32 + khalf * 16;
            #pragma unroll
            for (int mt = 0; mt < 4; mt++) {
                uint32_t ra = sb + (warpM + mt * 16 + arow) * 80 + koff;
                LDSM_X4(ah[mt][0], ah[mt][1], ah[mt][2], ah[mt][3], ra);
                LDSM_X4(al[mt][0], al[mt][1], al[mt][2], al[mt][3], ra + 10240);
            }
            #pragma unroll
            for (int g = 0; g < 2; g++) {
                uint32_t rb = sb + 20480 + (warpN + g * 16 + arow) * 80 + koff;
                uint32_t r0, r1, r2, r3;
                LDSM_X4(r0, r1, r2, r3, rb);
                bh[g*2+0][0] = r0; bh[g*2+0][1] = r2;
                bh[g*2+1][0] = r1; bh[g*2+1][1] = r3;
                LDSM_X4(r0, r1, r2, r3, rb + 10240);
                bl[g*2+0][0] = r0; bl[g*2+0][1] = r2;
                bl[g*2+1][0] = r1; bl[g*2+1][1] = r3;
            }
            #pragma unroll
            for (int mt = 0; mt < 4; mt++)
                #pragma unroll
                for (int nt = 0; nt < 4; nt++) {
                    MMA_BF16(acc[mt][nt], ah[mt], bh[nt]);
                    MMA_BF16(acc[mt][nt], ah[mt], bl[nt]);
                    MMA_BF16(acc[mt][nt], al[mt], bh[nt]);
                }
        }
        __syncthreads();
    }

    // ---- epilogue ----
    #pragma unroll
    for (int mt = 0; mt < 4; mt++) {
        #pragma unroll
        for (int nt = 0; nt < 4; nt++) {
            const int row0 = bm + warpM + mt * 16 + (lane >> 2);
            const int col  = bn + warpN + nt * 8 + (lane & 3) * 2;
            float2 bb = *(const float2*)(bias + col);
            float v0 = acc[mt][nt][0] + bb.x;
            float v1 = acc[mt][nt][1] + bb.y;
            float v2 = acc[mt][nt][2] + bb.x;
            float v3 = acc[mt][nt][3] + bb.y;
            if (EPI == 1) {
                float2 r0 = *(const float2*)(res + (size_t)row0 * N + col);
                float2 r1 = *(const float2*)(res + (size_t)(row0 + 8) * N + col);
                v0 += r0.x; v1 += r0.y; v2 += r1.x; v3 += r1.y;
            }
            if (EPI <= 1) {
                *(float2*)(outF + (size_t)row0 * N + col)       = make_float2(v0, v1);
                *(float2*)(outF + (size_t)(row0 + 8) * N + col) = make_float2(v2, v3);
            } else {
                if (EPI == 2) {
                    v0 = 0.5f * v0 * (1.0f + erff(v0 * 0.70710678118654752f));
                    v1 = 0.5f * v1 * (1.0f + erff(v1 * 0.70710678118654752f));
                    v2 = 0.5f * v2 * (1.0f + erff(v2 * 0.70710678118654752f));
                    v3 = 0.5f * v3 * (1.0f + erff(v3 * 0.70710678118654752f));
                }
                if (EPI == 3) { v0 *= oscale; v1 *= oscale; v2 *= oscale; v3 *= oscale; }
                float h0,l0,h1,l1,h2,l2,h3,l3;
                split1(v0,h0,l0); split1(v1,h1,l1);
                split1(v2,h2,l2); split1(v3,h3,l3);
                *(uint32_t*)(outH + (size_t)row0 * N + col)       = pack_bf2(h0, h1);
                *(uint32_t*)(outL + (size_t)row0 * N + col)       = pack_bf2(l0, l1);
                *(uint32_t*)(outH + (size_t)(row0 + 8) * N + col) = pack_bf2(h2, h3);
                *(uint32_t*)(outL + (size_t)(row0 + 8) * N + col) = pack_bf2(l2, l3);
            }
        }
    }
}

// ======================= tensor-core flash attention =======================
// Q pre-scaled by 1/8 in its projection epilogue. Inputs bf16 hi/lo.
// 128 q-rows per CTA, 64-key tiles, 8 warps x 16 q-rows.
// smem rows padded to 144B (64 bf16 + 16B pad).
#define AT_RS    144
#define AT_STAGE 36864   // Kh(9216) Kl Vh Vl per stage

__global__ __launch_bounds__(256)
void attn_mma(const __nv_bfloat16* __restrict__ Qh, const __nv_bfloat16* __restrict__ Ql,
              const __nv_bfloat16* __restrict__ Kh, const __nv_bfloat16* __restrict__ Kl,
              const __nv_bfloat16* __restrict__ Vh, const __nv_bfloat16* __restrict__ Vl,
              const float* __restrict__ mask,
              __nv_bfloat16* __restrict__ Oh, __nv_bfloat16* __restrict__ Ol)
{
    extern __shared__ char asmem[];
    __shared__ float msks[2][64];

    const int tid = threadIdx.x;
    const int wid = tid >> 5;
    const int lane = tid & 31;
    const int b = blockIdx.y >> 4;
    const int h = blockIdx.y & 15;
    const int q0 = blockIdx.x * 128;
    const uint32_t sb = smem_u32(asmem);
    const size_t hoff = (size_t)h * HDIM;

    // ---- stage Q (hi at 0, lo at 18432 — occupies stage0 region), extract frags
    #pragma unroll
    for (int t = 0; t < 4; t++) {
        int id = tid + t * 256;          // 1024 = 128 rows x 8 chunks
        int r = id >> 3, ch = id & 7;
        size_t src = (size_t)(b * SS + q0 + r) * DD + hoff + ch * 8;
        *(uint4*)(asmem + r * AT_RS + ch * 16)         = *(const uint4*)(Qh + src);
        *(uint4*)(asmem + 18432 + r * AT_RS + ch * 16) = *(const uint4*)(Ql + src);
    }
    __syncthreads();

    uint32_t aqh[4][4], aql[4][4];
    {
        const uint32_t arow = lane & 15, khalf = lane >> 4;
        #pragma unroll
        for (int c = 0; c < 4; c++) {
            uint32_t ra = sb + (wid * 16 + arow) * AT_RS + c * 32 + khalf * 16;
            LDSM_X4(aqh[c][0], aqh[c][1], aqh[c][2], aqh[c][3], ra);
            LDSM_X4(aql[c][0], aql[c][1], aql[c][2], aql[c][3], ra + 18432);
        }
    }
    __syncthreads();   // Q smem now reusable as pipeline stage 0

    float oacc[8][4];
    #pragma unroll
    for (int t = 0; t < 8; t++)
        #pragma unroll
        for (int r = 0; r < 4; r++) oacc[t][r] = 0.f;
    float m0 = -INFINITY, m1 = -INFINITY, l0 = 0.f, l1 = 0.f;

    // prefetch tile 0 into stage 0
    {
        #pragma unroll
        for (int t = 0; t < 2; t++) {
            int id = tid + t * 256;
            int r = id >> 3, ch = id & 7;
            size_t src = (size_t)(b * SS + r) * DD + hoff + ch * 8;
            uint32_t dst = sb + r * AT_RS + ch * 16;
            CP_ASYNC16(dst,         Kh + src);
            CP_ASYNC16(dst + 9216,  Kl + src);
            CP_ASYNC16(dst + 18432, Vh + src);
            CP_ASYNC16(dst + 27648, Vl + src);
        }
        if (tid < 16)
            CP_ASYNC16(smem_u32(&msks[0][0]) + tid * 16, mask + (size_t)b * SS + tid * 4);
        CP_COMMIT();
    }

    const uint32_t arow = lane & 15, khalf = lane >> 4;

    for (int it = 0; it < SS / 64; it++) {
        const int s = it & 1;
        if (it + 1 < SS / 64) {
            const int kt = (it + 1) * 64;
            uint32_t sb2 = sb + (s ^ 1) * AT_STAGE;
            #pragma unroll
            for (int t = 0; t < 2; t++) {
                int id = tid + t * 256;
                int r = id >> 3, ch = id & 7;
                size_t src = (size_t)(b * SS + kt + r) * DD + hoff + ch * 8;
                uint32_t dst = sb2 + r * AT_RS + ch * 16;
                CP_ASYNC16(dst,         Kh + src);
                CP_ASYNC16(dst + 9216,  Kl + src);
                CP_ASYNC16(dst + 18432, Vh + src);
                CP_ASYNC16(dst + 27648, Vl + src);
            }
            if (tid < 16)
                CP_ASYNC16(smem_u32(&msks[s ^ 1][0]) + tid * 16,
                           mask + (size_t)b * SS + kt + tid * 4);
        }
        CP_COMMIT();
        CP_WAIT1();
        __syncthreads();

        const uint32_t stg = sb + s * AT_STAGE;

        // ---- scores: 16 x 64 per warp
        float sc[8][4];
        #pragma unroll
        for (int t = 0; t < 8; t++)
            #pragma unroll
            for (int r = 0; r < 4; r++) sc[t][r] = 0.f;

        #pragma unroll
        for (int g = 0; g < 4; g++) {
            #pragma unroll
            for (int c = 0; c < 4; c++) {
                uint32_t rb = stg + (g * 16 + arow) * AT_RS + c * 32 + khalf * 16;
                uint32_t r0, r1, r2, r3, bh0[2], bh1[2], bl0[2], bl1[2];
                LDSM_X4(r0, r1, r2, r3, rb);
                bh0[0] = r0; bh0[1] = r2; bh1[0] = r1; bh1[1] = r3;
                LDSM_X4(r0, r1, r2, r3, rb + 9216);
                bl0[0] = r0; bl0[1] = r2; bl1[0] = r1; bl1[1] = r3;
                MMA_BF16(sc[2*g],   aqh[c], bh0);
                MMA_BF16(sc[2*g],   aqh[c], bl0);
                MMA_BF16(sc[2*g],   aql[c], bh0);
                MMA_BF16(sc[2*g+1], aqh[c], bh1);
                MMA_BF16(sc[2*g+1], aqh[c], bl1);
                MMA_BF16(sc[2*g+1], aql[c], bh1);
            }
        }

        // ---- mask + online softmax
        float mx0 = -INFINITY, mx1 = -INFINITY;
        #pragma unroll
        for (int t = 0; t < 8; t++) {
            float mk0 = msks[s][t * 8 + (lane & 3) * 2];
            float mk1 = msks[s][t * 8 + (lane & 3) * 2 + 1];
            sc[t][0] += mk0; sc[t][1] += mk1;
            sc[t][2] += mk0; sc[t][3] += mk1;
            mx0 = fmaxf(mx0, fmaxf(sc[t][0], sc[t][1]));
            mx1 = fmaxf(mx1, fmaxf(sc[t][2], sc[t][3]));
        }
        mx0 = fmaxf(mx0, __shfl_xor_sync(0xffffffffu, mx0, 1));
        mx0 = fmaxf(mx0, __shfl_xor_sync(0xffffffffu, mx0, 2));
        mx1 = fmaxf(mx1, __shfl_xor_sync(0xffffffffu, mx1, 1));
        mx1 = fmaxf(mx1, __shfl_xor_sync(0xffffffffu, mx1, 2));
        float mn0 = fmaxf(m0, mx0), mn1 = fmaxf(m1, mx1);
        float cr0 = __expf(m0 - mn0), cr1 = __expf(m1 - mn1);
        float sum0 = 0.f, sum1 = 0.f;
        #pragma unroll
        for (int t = 0; t < 8; t++) {
            sc[t][0] = __expf(sc[t][0] - mn0);
            sc[t][1] = __expf(sc[t][1] - mn0);
            sc[t][2] = __expf(sc[t][2] - mn1);
            sc[t][3] = __expf(sc[t][3] - mn1);
            sum0 += sc[t][0] + sc[t][1];
            sum1 += sc[t][2] + sc[t][3];
        }
        sum0 += __shfl_xor_sync(0xffffffffu, sum0, 1);
        sum0 += __shfl_xor_sync(0xffffffffu, sum0, 2);
        sum1 += __shfl_xor_sync(0xffffffffu, sum1, 1);
        sum1 += __shfl_xor_sync(0xffffffffu, sum1, 2);
        l0 = l0 * cr0 + sum0; l1 = l1 * cr1 + sum1;
        m0 = mn0; m1 = mn1;
        #pragma unroll
        for (int t = 0; t < 8; t++) {
            oacc[t][0] *= cr0; oacc[t][1] *= cr0;
            oacc[t][2] *= cr1; oacc[t][3] *= cr1;
        }

        // ---- PV: o += P @ V (3-product)
        #pragma unroll
        for (int c = 0; c < 4; c++) {
            // P frags (k-chunk c = keys 16c..16c+15) from sc[2c], sc[2c+1]
            uint32_t aph[4], apl[4];
            {
                float h0,lo0,h1,lo1;
                split1(sc[2*c][0],  h0, lo0); split1(sc[2*c][1],  h1, lo1);
                aph[0] = pack_bf2(h0, h1); apl[0] = pack_bf2(lo0, lo1);
                split1(sc[2*c][2],  h0, lo0); split1(sc[2*c][3],  h1, lo1);
                aph[1] = pack_bf2(h0, h1); apl[1] = pack_bf2(lo0, lo1);
                split1(sc[2*c+1][0], h0, lo0); split1(sc[2*c+1][1], h1, lo1);
                aph[2] = pack_bf2(h0, h1); apl[2] = pack_bf2(lo0, lo1);
                split1(sc[2*c+1][2], h0, lo0); split1(sc[2*c+1][3], h1, lo1);
                aph[3] = pack_bf2(h0, h1); apl[3] = pack_bf2(lo0, lo1);
            }
            // V frags: k rows 16c..16c+15, all 64 d-cols
            uint32_t bvh[8][2], bvl[8][2];
            #pragma unroll
            for (int nt2 = 0; nt2 < 4; nt2++) {
                uint32_t va = stg + 18432
                    + (c * 16 + (lane & 7) + 8 * ((lane >> 3) & 1)) * AT_RS
                    + (nt2 * 16 + 8 * (lane >> 4)) * 2;
                uint32_t r0, r1, r2, r3;
                LDSM_X4_T(r0, r1, r2, r3, va);
                bvh[2*nt2][0] = r0; bvh[2*nt2][1] = r1;
                bvh[2*nt2+1][0] = r2; bvh[2*nt2+1][1] = r3;
                LDSM_X4_T(r0, r1, r2, r3, va + 9216);
                bvl[2*nt2][0] = r0; bvl[2*nt2][1] = r1;
                bvl[2*nt2+1][0] = r2; bvl[2*nt2+1][1] = r3;
            }
            #pragma unroll
            for (int nt = 0; nt < 8; nt++) {
                MMA_BF16(oacc[nt], aph, bvh[nt]);
                MMA_BF16(oacc[nt], aph, bvl[nt]);
                MMA_BF16(oacc[nt], apl, bvh[nt]);
            }
        }
        __syncthreads();
    }

    // ---- epilogue: normalize, emit ctx as bf16 hi/lo
    float inv0 = 1.0f / l0, inv1 = 1.0f / l1;
    const size_t gr0 = (size_t)(b * SS + q0 + wid * 16 + (lane >> 2));
    const size_t gr1 = gr0 + 8;
    #pragma unroll
    for (int nt = 0; nt < 8; nt++) {
        const size_t d = hoff + nt * 8 + (lane & 3) * 2;
        float h0,lo0,h1,lo1;
        split1(oacc[nt][0] * inv0, h0, lo0); split1(oacc[nt][1] * inv0, h1, lo1);
        *(uint32_t*)(Oh + gr0 * DD + d) = pack_bf2(h0, h1);
        *(uint32_t*)(Ol + gr0 * DD + d) = pack_bf2(lo0, lo1);
        split1(oacc[nt][2] * inv1, h0, lo0); split1(oacc[nt][3] * inv1, h1, lo1);
        *(uint32_t*)(Oh + gr1 * DD + d) = pack_bf2(h0, h1);
        *(uint32_t*)(Ol + gr1 * DD + d) = pack_bf2(lo0, lo1);
    }
}

// ======================= LayerNorm =======================
template<bool EMIT>
__global__ __launch_bounds__(256)
void ln_kernel(const float* __restrict__ X, const float* __restrict__ gw,
               const float* __restrict__ bw, float* __restrict__ Y,
               __nv_bfloat16* __restrict__ Yh, __nv_bfloat16* __restrict__ Yl)
{
    __shared__ float red[2][8];
    const int row = blockIdx.x;
    const int tid = threadIdx.x;
    const float* x = X + (size_t)row * DD;

    float4 v = *(const float4*)(x + tid * 4);
    float s  = v.x + v.y + v.z + v.w;
    float sq = v.x*v.x + v.y*v.y + v.z*v.z + v.w*v.w;
    #pragma unroll
    for (int w = 16; w > 0; w >>= 1) {
        s  += __shfl_xor_sync(0xffffffffu, s,  w);
        sq += __shfl_xor_sync(0xffffffffu, sq, w);
    }
    if ((tid & 31) == 0) { red[0][tid >> 5] = s; red[1][tid >> 5] = sq; }
    __syncthreads();
    float tot = 0.f, totq = 0.f;
    #pragma unroll
    for (int i = 0; i < 8; i++) { tot += red[0][i]; totq += red[1][i]; }

    float mean = tot * (1.0f / DD);
    float var  = totq * (1.0f / DD) - mean * mean;
    float inv  = rsqrtf(var + 1e-12f);

    float4 gg = *(const float4*)(gw + tid * 4);
    float4 bb = *(const float4*)(bw + tid * 4);
    float4 out;
    out.x = (v.x - mean) * inv * gg.x + bb.x;
    out.y = (v.y - mean) * inv * gg.y + bb.y;
    out.z = (v.z - mean) * inv * gg.z + bb.z;
    out.w = (v.w - mean) * inv * gg.w + bb.w;
    *(float4*)(Y + (size_t)row * DD + tid * 4) = out;

    if (EMIT) {
        float hx,lx,hy,ly,hz,lz,hw,lw;
        split1(out.x,hx,lx); split1(out.y,hy,ly);
        split1(out.z,hz,lz); split1(out.w,hw,lw);
        size_t ob = (size_t)row * DD + tid * 4;
        *(uint2*)(Yh + ob) = make_uint2(pack_bf2(hx,hy), pack_bf2(hz,hw));
        *(uint2*)(Yl + ob) = make_uint2(pack_bf2(lx,ly), pack_bf2(lz,lw));
    }
}

// ======================= host launch =======================
extern "C" void kernel_launch(void* const* d_in, const int* in_sizes, int n_in,
                              void* d_out, int out_size)
{
    const float* x    = (const float*)d_in[0];
    const float* mask = (const float*)d_in[1];
    const float* Wq   = (const float*)d_in[2];
    const float* bq   = (const float*)d_in[3];
    const float* Wk   = (const float*)d_in[4];
    const float* bk   = (const float*)d_in[5];
    const float* Wv   = (const float*)d_in[6];
    const float* bv   = (const float*)d_in[7];
    const float* Wo   = (const float*)d_in[8];
    const float* bo   = (const float*)d_in[9];
    const float* ln1g = (const float*)d_in[10];
    const float* ln1b = (const float*)d_in[11];
    const float* Wi   = (const float*)d_in[12];
    const float* bi   = (const float*)d_in[13];
    const float* Wo2  = (const float*)d_in[14];
    const float* bo2  = (const float*)d_in[15];
    const float* ln2g = (const float*)d_in[16];
    const float* ln2b = (const float*)d_in[17];

    float *t1, *att, *t2;
    __nv_bfloat16 *xh, *xl, *qh, *ql, *kh, *kl, *vh, *vl, *cth, *ctl, *ath, *atl, *hh, *hl;
    __nv_bfloat16 *wqh,*wql,*wkh,*wkl,*wvh,*wvl,*woh,*wol,*wih,*wil,*w2h,*w2l;
    cudaGetSymbolAddress((void**)&t1,  g_t1);
    cudaGetSymbolAddress((void**)&att, g_att);
    cudaGetSymbolAddress((void**)&t2,  g_t2);
    cudaGetSymbolAddress((void**)&xh,  g_xh);
    cudaGetSymbolAddress((void**)&xl,  g_xl);
    cudaGetSymbolAddress((void**)&qh,  g_qh); cudaGetSymbolAddress((void**)&ql, g_ql);
    cudaGetSymbolAddress((void**)&kh,  g_kh); cudaGetSymbolAddress((void**)&kl, g_kl);
    cudaGetSymbolAddress((void**)&vh,  g_vh); cudaGetSymbolAddress((void**)&vl, g_vl);
    cudaGetSymbolAddress((void**)&cth, g_cth);
    cudaGetSymbolAddress((void**)&ctl, g_ctl);
    cudaGetSymbolAddress((void**)&ath, g_ath);
    cudaGetSymbolAddress((void**)&atl, g_atl);
    cudaGetSymbolAddress((void**)&hh,  g_hh);
    cudaGetSymbolAddress((void**)&hl,  g_hl);
    cudaGetSymbolAddress((void**)&wqh, g_wqh); cudaGetSymbolAddress((void**)&wql, g_wql);
    cudaGetSymbolAddress((void**)&wkh, g_wkh); cudaGetSymbolAddress((void**)&wkl, g_wkl);
    cudaGetSymbolAddress((void**)&wvh, g_wvh); cudaGetSymbolAddress((void**)&wvl, g_wvl);
    cudaGetSymbolAddress((void**)&woh, g_woh); cudaGetSymbolAddress((void**)&wol, g_wol);
    cudaGetSymbolAddress((void**)&wih, g_wih); cudaGetSymbolAddress((void**)&wil, g_wil);
    cudaGetSymbolAddress((void**)&w2h, g_w2h); cudaGetSymbolAddress((void**)&w2l, g_w2l);

    const int GEMM_SMEM = 2 * STG_BYTES;   // 81920
    cudaFuncSetAttribute(mma_gemm<0>, cudaFuncAttributeMaxDynamicSharedMemorySize, GEMM_SMEM);
    cudaFuncSetAttribute(mma_gemm<1>, cudaFuncAttributeMaxDynamicSharedMemorySize, GEMM_SMEM);
    cudaFuncSetAttribute(mma_gemm<2>, cudaFuncAttributeMaxDynamicSharedMemorySize, GEMM_SMEM);
    cudaFuncSetAttribute(mma_gemm<3>, cudaFuncAttributeMaxDynamicSharedMemorySize, GEMM_SMEM);
    const int ATTN_SMEM = 2 * AT_STAGE;    // 73728
    cudaFuncSetAttribute(attn_mma, cudaFuncAttributeMaxDynamicSharedMemorySize, ATTN_SMEM);

    // weight transforms
    wtrans_kernel<<<dim3(DD/32, DD/32), 256>>>(Wq, wqh, wql, DD, DD);
    wtrans_kernel<<<dim3(DD/32, DD/32), 256>>>(Wk, wkh, wkl, DD, DD);
    wtrans_kernel<<<dim3(DD/32, DD/32), 256>>>(Wv, wvh, wvl, DD, DD);
    wtrans_kernel<<<dim3(DD/32, DD/32), 256>>>(Wo, woh, wol, DD, DD);
    wtrans_kernel<<<dim3(DFFN/32, DD/32), 256>>>(Wi, wih, wil, DD, DFFN);
    wtrans_kernel<<<dim3(DD/32, DFFN/32), 256>>>(Wo2, w2h, w2l, DFFN, DD);

    // decompose input
    decomp_kernel<<<(MTOT*DD/4 + 255)/256, 256>>>((const float4*)x, (uint2*)xh, (uint2*)xl, MTOT*DD/4);

    dim3 gQ(DD/128, MTOT/128);     // 8 x 64
    dim3 gF1(DFFN/128, MTOT/128);  // 32 x 64

    // QKV projections -> bf16 hi/lo (Q pre-scaled by 1/8)
    mma_gemm<3><<<gQ, 256, GEMM_SMEM>>>(xh, xl, wqh, wql, bq, nullptr, nullptr, qh, ql, MTOT, DD, DD, 0.125f);
    mma_gemm<3><<<gQ, 256, GEMM_SMEM>>>(xh, xl, wkh, wkl, bk, nullptr, nullptr, kh, kl, MTOT, DD, DD, 1.0f);
    mma_gemm<3><<<gQ, 256, GEMM_SMEM>>>(xh, xl, wvh, wvl, bv, nullptr, nullptr, vh, vl, MTOT, DD, DD, 1.0f);

    // attention (tensor cores) -> ctx hi/lo
    attn_mma<<<dim3(SS/128, BB*HH), 256, ATTN_SMEM>>>(qh, ql, kh, kl, vh, vl, mask, cth, ctl);

    // O projection + residual -> t1; LN1 -> att (+hi/lo)
    mma_gemm<1><<<gQ, 256, GEMM_SMEM>>>(cth, ctl, woh, wol, bo, x, t1, nullptr, nullptr, MTOT, DD, DD, 1.0f);
    ln_kernel<true><<<MTOT, 256>>>(t1, ln1g, ln1b, att, ath, atl);

    // FFN
    mma_gemm<2><<<gF1, 256, GEMM_SMEM>>>(ath, atl, wih, wil, bi, nullptr, nullptr, hh, hl, MTOT, DFFN, DD, 1.0f);
    mma_gemm<1><<<gQ, 256, GEMM_SMEM>>>(hh, hl, w2h, w2l, bo2, att, t2, nullptr, nullptr, MTOT, DD, DFFN, 1.0f);
    ln_kernel<false><<<MTOT, 256>>>(t2, ln2g, ln2b, (float*)d_out, nullptr, nullptr);
}

// round 6
// speedup vs baseline: 3.6023x; 2.2138x over previous
#include <cuda_runtime.h>
#include <cuda_bf16.h>
#include <math.h>
#include <stdint.h>
#include <stddef.h>

#define BB   4
#define SS   2048
#define DD   1024
#define HH   16
#define HDIM 64
#define DFFN 4096
#define MTOT (BB*SS)   // 8192

// ======================= scratch =======================
__device__ float g_t1 [(size_t)MTOT*DD];
__device__ float g_att[(size_t)MTOT*DD];
__device__ float g_t2 [(size_t)MTOT*DD];
__device__ __nv_bfloat16 g_xh [(size_t)MTOT*DD];
__device__ __nv_bfloat16 g_qh [(size_t)MTOT*DD];
__device__ __nv_bfloat16 g_kh [(size_t)MTOT*DD];
__device__ __nv_bfloat16 g_vh [(size_t)MTOT*DD];
__device__ __nv_bfloat16 g_ct [(size_t)MTOT*DD];
__device__ __nv_bfloat16 g_ath[(size_t)MTOT*DD], g_atl[(size_t)MTOT*DD];
__device__ __nv_bfloat16 g_hh [(size_t)MTOT*DFFN], g_hl [(size_t)MTOT*DFFN];
// transposed-decomposed weights [N, K]
__device__ __nv_bfloat16 g_wqh[(size_t)DD*DD],  g_wql[(size_t)DD*DD];
__device__ __nv_bfloat16 g_wkh[(size_t)DD*DD],  g_wkl[(size_t)DD*DD];
__device__ __nv_bfloat16 g_wvh[(size_t)DD*DD],  g_wvl[(size_t)DD*DD];
__device__ __nv_bfloat16 g_woh[(size_t)DD*DD],  g_wol[(size_t)DD*DD];
__device__ __nv_bfloat16 g_wih[(size_t)DD*DFFN], g_wil[(size_t)DD*DFFN];
__device__ __nv_bfloat16 g_w2h[(size_t)DFFN*DD], g_w2l[(size_t)DFFN*DD];

// ======================= helpers =======================
__device__ __forceinline__ uint32_t smem_u32(const void* p) {
    uint32_t a;
    asm("{ .reg .u64 t; cvta.to.shared.u64 t, %1; cvt.u32.u64 %0, t; }" : "=r"(a) : "l"(p));
    return a;
}
__device__ __forceinline__ uint32_t pack_bf2(float a, float b) {
    __nv_bfloat162 t = __floats2bfloat162_rn(a, b);
    return *reinterpret_cast<uint32_t*>(&t);
}
__device__ __forceinline__ void split1(float v, float& hi, float& lo) {
    __nv_bfloat16 h = __float2bfloat16_rn(v);
    hi = __bfloat162float(h);
    lo = v - hi;
}

#define CP_ASYNC16(dst, src) \
    asm volatile("cp.async.cg.shared.global [%0], [%1], 16;" :: "r"(dst), "l"(src) : "memory")
#define CP_COMMIT() asm volatile("cp.async.commit_group;" ::: "memory")
#define CP_WAIT1()  asm volatile("cp.async.wait_group 1;" ::: "memory")

#define LDSM_X4(r0, r1, r2, r3, addr) \
    asm volatile("ldmatrix.sync.aligned.m8n8.x4.shared.b16 {%0,%1,%2,%3}, [%4];" \
        : "=r"(r0), "=r"(r1), "=r"(r2), "=r"(r3) : "r"(addr))

#define LDSM_X4_T(r0, r1, r2, r3, addr) \
    asm volatile("ldmatrix.sync.aligned.m8n8.x4.trans.shared.b16 {%0,%1,%2,%3}, [%4];" \
        : "=r"(r0), "=r"(r1), "=r"(r2), "=r"(r3) : "r"(addr))

#define MMA_BF16(d, a, b) \
    asm volatile("mma.sync.aligned.m16n8k16.row.col.f32.bf16.bf16.f32 " \
        "{%0,%1,%2,%3}, {%4,%5,%6,%7}, {%8,%9}, {%0,%1,%2,%3};" \
        : "+f"((d)[0]), "+f"((d)[1]), "+f"((d)[2]), "+f"((d)[3]) \
        : "r"((a)[0]), "r"((a)[1]), "r"((a)[2]), "r"((a)[3]), \
          "r"((b)[0]), "r"((b)[1]))

// fp32 -> bf16 (hi only)
__global__ __launch_bounds__(256)
void cvt_kernel(const float4* __restrict__ in, uint2* __restrict__ oh, int n4)
{
    int i = blockIdx.x * 256 + threadIdx.x;
    if (i >= n4) return;
    float4 v = in[i];
    oh[i] = make_uint2(pack_bf2(v.x, v.y), pack_bf2(v.z, v.w));
}

// transpose + decompose: W [K,N] fp32 -> Th/Tl [N,K] bf16
__global__ __launch_bounds__(256)
void wtrans_kernel(const float* __restrict__ W, __nv_bfloat16* __restrict__ Th,
                   __nv_bfloat16* __restrict__ Tl, int K, int N)
{
    __shared__ float tile[32][33];
    int n0 = blockIdx.x * 32, k0 = blockIdx.y * 32;
    int tx = threadIdx.x & 31, ty = threadIdx.x >> 5; // 32 x 8
    #pragma unroll
    for (int i = ty; i < 32; i += 8)
        tile[i][tx] = W[(size_t)(k0 + i) * N + n0 + tx];
    __syncthreads();
    #pragma unroll
    for (int i = ty; i < 32; i += 8) {
        float v = tile[tx][i];
        float h, l; split1(v, h, l);
        size_t o = (size_t)(n0 + i) * K + k0 + tx;
        Th[o] = __float2bfloat16_rn(h);
        Tl[o] = __float2bfloat16_rn(l);
    }
}

// ======================= single-product bf16 GEMM core =======================
// C[M,N] = A[M,K] @ B^T (B stored [N,K]); plain bf16 operands.
// EPI 1: +bias +res -> fp32 ; EPI 3: (+bias)*scale -> bf16
// stage: A@0 (10240 = 128 rows x 80B), B@10240; stage stride 20480
template<int EPI>
__device__ __forceinline__
void gemm1_core(char* dsm, const __nv_bfloat16* __restrict__ A,
                const __nv_bfloat16* __restrict__ B,
                const float* __restrict__ bias, const float* __restrict__ res,
                float* __restrict__ outF, __nv_bfloat16* __restrict__ outB,
                int M, int N, int K, float oscale)
{
    const int tid = threadIdx.x;
    const int wid = tid >> 5;
    const int lane = tid & 31;
    const int bm = blockIdx.y * 128;
    const int bn = blockIdx.x * 128;
    const int warpM = (wid & 1) * 64;
    const int warpN = (wid >> 1) * 32;
    const uint32_t sbase = smem_u32(dsm);

    float acc[4][4][4];
    #pragma unroll
    for (int mt = 0; mt < 4; mt++)
        #pragma unroll
        for (int nt = 0; nt < 4; nt++)
            #pragma unroll
            for (int r = 0; r < 4; r++) acc[mt][nt][r] = 0.f;

    const int NC = K >> 5;   // BK = 32

    {
        #pragma unroll
        for (int t = 0; t < 2; t++) {
            int id = tid + t * 256;            // 0..511
            int row = id >> 2, ch = id & 3;
            uint32_t doff = sbase + row * 80 + ch * 16;
            CP_ASYNC16(doff,         A + (size_t)(bm + row) * K + ch * 8);
            CP_ASYNC16(doff + 10240, B + (size_t)(bn + row) * K + ch * 8);
        }
        CP_COMMIT();
    }

    for (int c = 0; c < NC; c++) {
        const int s = c & 1;
        if (c + 1 < NC) {
            const int k0 = (c + 1) << 5;
            uint32_t sb2 = sbase + (s ^ 1) * 20480;
            #pragma unroll
            for (int t = 0; t < 2; t++) {
                int id = tid + t * 256;
                int row = id >> 2, ch = id & 3;
                uint32_t doff = sb2 + row * 80 + ch * 16;
                CP_ASYNC16(doff,         A + (size_t)(bm + row) * K + k0 + ch * 8);
                CP_ASYNC16(doff + 10240, B + (size_t)(bn + row) * K + k0 + ch * 8);
            }
        }
        CP_COMMIT();
        CP_WAIT1();
        __syncthreads();

        const uint32_t sb = sbase + s * 20480;
        const uint32_t arow = (lane & 15);
        const uint32_t khalf = (lane >> 4);
        #pragma unroll
        for (int ks = 0; ks < 2; ks++) {
            uint32_t ah[4][4], bh[4][2];
            const uint32_t koff = ks * 32 + khalf * 16;
            #pragma unroll
            for (int mt = 0; mt < 4; mt++) {
                uint32_t ra = sb + (warpM + mt * 16 + arow) * 80 + koff;
                LDSM_X4(ah[mt][0], ah[mt][1], ah[mt][2], ah[mt][3], ra);
            }
            #pragma unroll
            for (int g = 0; g < 2; g++) {
                uint32_t rb = sb + 10240 + (warpN + g * 16 + arow) * 80 + koff;
                uint32_t r0, r1, r2, r3;
                LDSM_X4(r0, r1, r2, r3, rb);
                bh[g*2+0][0] = r0; bh[g*2+0][1] = r2;
                bh[g*2+1][0] = r1; bh[g*2+1][1] = r3;
            }
            #pragma unroll
            for (int mt = 0; mt < 4; mt++)
                #pragma unroll
                for (int nt = 0; nt < 4; nt++)
                    MMA_BF16(acc[mt][nt], ah[mt], bh[nt]);
        }
        __syncthreads();
    }

    #pragma unroll
    for (int mt = 0; mt < 4; mt++) {
        #pragma unroll
        for (int nt = 0; nt < 4; nt++) {
            const int row0 = bm + warpM + mt * 16 + (lane >> 2);
            const int col  = bn + warpN + nt * 8 + (lane & 3) * 2;
            float2 bb = *(const float2*)(bias + col);
            float v0 = acc[mt][nt][0] + bb.x;
            float v1 = acc[mt][nt][1] + bb.y;
            float v2 = acc[mt][nt][2] + bb.x;
            float v3 = acc[mt][nt][3] + bb.y;
            if (EPI == 1) {
                float2 r0 = *(const float2*)(res + (size_t)row0 * N + col);
                float2 r1 = *(const float2*)(res + (size_t)(row0 + 8) * N + col);
                v0 += r0.x; v1 += r0.y; v2 += r1.x; v3 += r1.y;
                *(float2*)(outF + (size_t)row0 * N + col)       = make_float2(v0, v1);
                *(float2*)(outF + (size_t)(row0 + 8) * N + col) = make_float2(v2, v3);
            }
            if (EPI == 3) {
                v0 *= oscale; v1 *= oscale; v2 *= oscale; v3 *= oscale;
                *(uint32_t*)(outB + (size_t)row0 * N + col)       = pack_bf2(v0, v1);
                *(uint32_t*)(outB + (size_t)(row0 + 8) * N + col) = pack_bf2(v2, v3);
            }
        }
    }
}

// fused QKV: grid.z selects weight/bias/output
__global__ __launch_bounds__(256, 2)
void qkv_gemm(const __nv_bfloat16* __restrict__ A,
              const __nv_bfloat16* __restrict__ Bq, const __nv_bfloat16* __restrict__ Bk,
              const __nv_bfloat16* __restrict__ Bv,
              const float* __restrict__ bq, const float* __restrict__ bk,
              const float* __restrict__ bv,
              __nv_bfloat16* __restrict__ oq, __nv_bfloat16* __restrict__ ok,
              __nv_bfloat16* __restrict__ ov, int M, int N, int K)
{
    extern __shared__ char dsm[];
    const int z = blockIdx.z;
    const __nv_bfloat16* B = (z == 0) ? Bq : (z == 1) ? Bk : Bv;
    const float* bias      = (z == 0) ? bq : (z == 1) ? bk : bv;
    __nv_bfloat16* out     = (z == 0) ? oq : (z == 1) ? ok : ov;
    float sc               = (z == 0) ? 0.125f : 1.0f;
    gemm1_core<3>(dsm, A, B, bias, nullptr, nullptr, out, M, N, K, sc);
}

__global__ __launch_bounds__(256, 2)
void oproj_gemm(const __nv_bfloat16* __restrict__ A, const __nv_bfloat16* __restrict__ B,
                const float* __restrict__ bias, const float* __restrict__ res,
                float* __restrict__ outF, int M, int N, int K)
{
    extern __shared__ char dsm[];
    gemm1_core<1>(dsm, A, B, bias, res, outF, nullptr, M, N, K, 1.0f);
}

// ======================= 3-product split-bf16 GEMM (FFN) =======================
#define STG_BYTES 40960

template<int EPI>   // 1: +bias+res -> fp32 ; 2: +bias,gelu -> bf16 hi/lo
__global__ __launch_bounds__(256)
void mma_gemm(const __nv_bfloat16* __restrict__ Ah, const __nv_bfloat16* __restrict__ Al,
              const __nv_bfloat16* __restrict__ Bh, const __nv_bfloat16* __restrict__ Bl,
              const float* __restrict__ bias, const float* __restrict__ res,
              float* __restrict__ outF, __nv_bfloat16* __restrict__ outH,
              __nv_bfloat16* __restrict__ outL, int M, int N, int K)
{
    extern __shared__ char dsm[];
    const int tid = threadIdx.x;
    const int wid = tid >> 5;
    const int lane = tid & 31;
    const int bm = blockIdx.y * 128;
    const int bn = blockIdx.x * 128;
    const int warpM = (wid & 1) * 64;
    const int warpN = (wid >> 1) * 32;
    const uint32_t sbase = smem_u32(dsm);

    float acc[4][4][4];
    #pragma unroll
    for (int mt = 0; mt < 4; mt++)
        #pragma unroll
        for (int nt = 0; nt < 4; nt++)
            #pragma unroll
            for (int r = 0; r < 4; r++) acc[mt][nt][r] = 0.f;

    const int NC = K >> 5;

    {
        #pragma unroll
        for (int t = 0; t < 2; t++) {
            int id = tid + t * 256;
            int row = id >> 2, ch = id & 3;
            uint32_t doff = sbase + row * 80 + ch * 16;
            size_t ga = (size_t)(bm + row) * K + ch * 8;
            size_t gb = (size_t)(bn + row) * K + ch * 8;
            CP_ASYNC16(doff,          Ah + ga);
            CP_ASYNC16(doff + 10240,  Al + ga);
            CP_ASYNC16(doff + 20480,  Bh + gb);
            CP_ASYNC16(doff + 30720,  Bl + gb);
        }
        CP_COMMIT();
    }

    for (int c = 0; c < NC; c++) {
        const int s = c & 1;
        if (c + 1 < NC) {
            const int k0 = (c + 1) << 5;
            uint32_t sb2 = sbase + (s ^ 1) * STG_BYTES;
            #pragma unroll
            for (int t = 0; t < 2; t++) {
                int id = tid + t * 256;
                int row = id >> 2, ch = id & 3;
                uint32_t doff = sb2 + row * 80 + ch * 16;
                size_t ga = (size_t)(bm + row) * K + k0 + ch * 8;
                size_t gb = (size_t)(bn + row) * K + k0 + ch * 8;
                CP_ASYNC16(doff,          Ah + ga);
                CP_ASYNC16(doff + 10240,  Al + ga);
                CP_ASYNC16(doff + 20480,  Bh + gb);
                CP_ASYNC16(doff + 30720,  Bl + gb);
            }
        }
        CP_COMMIT();
        CP_WAIT1();
        __syncthreads();

        const uint32_t sb = sbase + s * STG_BYTES;
        const uint32_t arow = (lane & 15);
        const uint32_t khalf = (lane >> 4);
        #pragma unroll
        for (int ks = 0; ks < 2; ks++) {
            uint32_t ah[4][4], al[4][4], bh[4][2], bl[4][2];
            const uint32_t koff = ks * 32 + khalf * 16;
            #pragma unroll
            for (int mt = 0; mt < 4; mt++) {
                uint32_t ra = sb + (warpM + mt * 16 + arow) * 80 + koff;
                LDSM_X4(ah[mt][0], ah[mt][1], ah[mt][2], ah[mt][3], ra);
                LDSM_X4(al[mt][0], al[mt][1], al[mt][2], al[mt][3], ra + 10240);
            }
            #pragma unroll
            for (int g = 0; g < 2; g++) {
                uint32_t rb = sb + 20480 + (warpN + g * 16 + arow) * 80 + koff;
                uint32_t r0, r1, r2, r3;
                LDSM_X4(r0, r1, r2, r3, rb);
                bh[g*2+0][0] = r0; bh[g*2+0][1] = r2;
                bh[g*2+1][0] = r1; bh[g*2+1][1] = r3;
                LDSM_X4(r0, r1, r2, r3, rb + 10240);
                bl[g*2+0][0] = r0; bl[g*2+0][1] = r2;
                bl[g*2+1][0] = r1; bl[g*2+1][1] = r3;
            }
            #pragma unroll
            for (int mt = 0; mt < 4; mt++)
                #pragma unroll
                for (int nt = 0; nt < 4; nt++) {
                    MMA_BF16(acc[mt][nt], ah[mt], bh[nt]);
                    MMA_BF16(acc[mt][nt], ah[mt], bl[nt]);
                    MMA_BF16(acc[mt][nt], al[mt], bh[nt]);
                }
        }
        __syncthreads();
    }

    #pragma unroll
    for (int mt = 0; mt < 4; mt++) {
        #pragma unroll
        for (int nt = 0; nt < 4; nt++) {
            const int row0 = bm + warpM + mt * 16 + (lane >> 2);
            const int col  = bn + warpN + nt * 8 + (lane & 3) * 2;
            float2 bb = *(const float2*)(bias + col);
            float v0 = acc[mt][nt][0] + bb.x;
            float v1 = acc[mt][nt][1] + bb.y;
            float v2 = acc[mt][nt][2] + bb.x;
            float v3 = acc[mt][nt][3] + bb.y;
            if (EPI == 1) {
                float2 r0 = *(const float2*)(res + (size_t)row0 * N + col);
                float2 r1 = *(const float2*)(res + (size_t)(row0 + 8) * N + col);
                v0 += r0.x; v1 += r0.y; v2 += r1.x; v3 += r1.y;
                *(float2*)(outF + (size_t)row0 * N + col)       = make_float2(v0, v1);
                *(float2*)(outF + (size_t)(row0 + 8) * N + col) = make_float2(v2, v3);
            }
            if (EPI == 2) {
                v0 = 0.5f * v0 * (1.0f + erff(v0 * 0.70710678118654752f));
                v1 = 0.5f * v1 * (1.0f + erff(v1 * 0.70710678118654752f));
                v2 = 0.5f * v2 * (1.0f + erff(v2 * 0.70710678118654752f));
                v3 = 0.5f * v3 * (1.0f + erff(v3 * 0.70710678118654752f));
                float h0,l0,h1,l1,h2,l2,h3,l3;
                split1(v0,h0,l0); split1(v1,h1,l1);
                split1(v2,h2,l2); split1(v3,h3,l3);
                *(uint32_t*)(outH + (size_t)row0 * N + col)       = pack_bf2(h0, h1);
                *(uint32_t*)(outL + (size_t)row0 * N + col)       = pack_bf2(l0, l1);
                *(uint32_t*)(outH + (size_t)(row0 + 8) * N + col) = pack_bf2(h2, h3);
                *(uint32_t*)(outL + (size_t)(row0 + 8) * N + col) = pack_bf2(l2, l3);
            }
        }
    }
}

// ======================= bf16 flash attention =======================
// Q pre-scaled by 1/8. 128 q-rows/CTA, 64-key tiles, 8 warps x 16 q-rows.
// stage = K(9216 = 64 x 144B) + V(9216); 2 stages.
#define AT_RS    144
#define AT_STAGE 18432

__global__ __launch_bounds__(256, 2)
void attn_bf16(const __nv_bfloat16* __restrict__ Qh, const __nv_bfloat16* __restrict__ Kh,
               const __nv_bfloat16* __restrict__ Vh, const float* __restrict__ mask,
               __nv_bfloat16* __restrict__ O)
{
    extern __shared__ char asmem[];
    __shared__ float msks[2][64];

    const int tid = threadIdx.x;
    const int wid = tid >> 5;
    const int lane = tid & 31;
    const int b = blockIdx.y >> 4;
    const int h = blockIdx.y & 15;
    const int q0 = blockIdx.x * 128;
    const uint32_t sb = smem_u32(asmem);
    const size_t hoff = (size_t)h * HDIM;

    // stage Q into stage0 region (128 rows x 144B = 18432), extract frags
    #pragma unroll
    for (int t = 0; t < 4; t++) {
        int id = tid + t * 256;          // 1024 = 128 rows x 8 chunks
        int r = id >> 3, ch = id & 7;
        size_t src = (size_t)(b * SS + q0 + r) * DD + hoff + ch * 8;
        *(uint4*)(asmem + r * AT_RS + ch * 16) = *(const uint4*)(Qh + src);
    }
    __syncthreads();

    uint32_t aq[4][4];
    {
        const uint32_t arow = lane & 15, khalf = lane >> 4;
        #pragma unroll
        for (int c = 0; c < 4; c++) {
            uint32_t ra = sb + (wid * 16 + arow) * AT_RS + c * 32 + khalf * 16;
            LDSM_X4(aq[c][0], aq[c][1], aq[c][2], aq[c][3], ra);
        }
    }
    __syncthreads();   // Q smem now reusable as stage 0

    float oacc[8][4];
    #pragma unroll
    for (int t = 0; t < 8; t++)
        #pragma unroll
        for (int r = 0; r < 4; r++) oacc[t][r] = 0.f;
    float m0 = -INFINITY, m1 = -INFINITY, l0 = 0.f, l1 = 0.f;

    // prefetch tile 0
    {
        #pragma unroll
        for (int t = 0; t < 2; t++) {
            int id = tid + t * 256;      // 512 = 64 rows x 8 chunks
            int r = id >> 3, ch = id & 7;
            size_t src = (size_t)(b * SS + r) * DD + hoff + ch * 8;
            uint32_t dst = sb + r * AT_RS + ch * 16;
            CP_ASYNC16(dst,        Kh + src);
            CP_ASYNC16(dst + 9216, Vh + src);
        }
        if (tid < 16)
            CP_ASYNC16(smem_u32(&msks[0][0]) + tid * 16, mask + (size_t)b * SS + tid * 4);
        CP_COMMIT();
    }

    const uint32_t arow = lane & 15, khalf = lane >> 4;

    for (int it = 0; it < SS / 64; it++) {
        const int s = it & 1;
        if (it + 1 < SS / 64) {
            const int kt = (it + 1) * 64;
            uint32_t sb2 = sb + (s ^ 1) * AT_STAGE;
            #pragma unroll
            for (int t = 0; t < 2; t++) {
                int id = tid + t * 256;
                int r = id >> 3, ch = id & 7;
                size_t src = (size_t)(b * SS + kt + r) * DD + hoff + ch * 8;
                uint32_t dst = sb2 + r * AT_RS + ch * 16;
                CP_ASYNC16(dst,        Kh + src);
                CP_ASYNC16(dst + 9216, Vh + src);
            }
            if (tid < 16)
                CP_ASYNC16(smem_u32(&msks[s ^ 1][0]) + tid * 16,
                           mask + (size_t)b * SS + kt + tid * 4);
        }
        CP_COMMIT();
        CP_WAIT1();
        __syncthreads();

        const uint32_t stg = sb + s * AT_STAGE;

        // ---- scores: 16 x 64 per warp
        float sc[8][4];
        #pragma unroll
        for (int t = 0; t < 8; t++)
            #pragma unroll
            for (int r = 0; r < 4; r++) sc[t][r] = 0.f;

        #pragma unroll
        for (int g = 0; g < 4; g++) {
            #pragma unroll
            for (int c = 0; c < 4; c++) {
                uint32_t rb = stg + (g * 16 + arow) * AT_RS + c * 32 + khalf * 16;
                uint32_t r0, r1, r2, r3, bh0[2], bh1[2];
                LDSM_X4(r0, r1, r2, r3, rb);
                bh0[0] = r0; bh0[1] = r2; bh1[0] = r1; bh1[1] = r3;
                MMA_BF16(sc[2*g],   aq[c], bh0);
                MMA_BF16(sc[2*g+1], aq[c], bh1);
            }
        }

        // ---- mask + online softmax
        float mx0 = -INFINITY, mx1 = -INFINITY;
        #pragma unroll
        for (int t = 0; t < 8; t++) {
            float mk0 = msks[s][t * 8 + (lane & 3) * 2];
            float mk1 = msks[s][t * 8 + (lane & 3) * 2 + 1];
            sc[t][0] += mk0; sc[t][1] += mk1;
            sc[t][2] += mk0; sc[t][3] += mk1;
            mx0 = fmaxf(mx0, fmaxf(sc[t][0], sc[t][1]));
            mx1 = fmaxf(mx1, fmaxf(sc[t][2], sc[t][3]));
        }
        mx0 = fmaxf(mx0, __shfl_xor_sync(0xffffffffu, mx0, 1));
        mx0 = fmaxf(mx0, __shfl_xor_sync(0xffffffffu, mx0, 2));
        mx1 = fmaxf(mx1, __shfl_xor_sync(0xffffffffu, mx1, 1));
        mx1 = fmaxf(mx1, __shfl_xor_sync(0xffffffffu, mx1, 2));
        float mn0 = fmaxf(m0, mx0), mn1 = fmaxf(m1, mx1);
        float cr0 = __expf(m0 - mn0), cr1 = __expf(m1 - mn1);
        float sum0 = 0.f, sum1 = 0.f;
        #pragma unroll
        for (int t = 0; t < 8; t++) {
            sc[t][0] = __expf(sc[t][0] - mn0);
            sc[t][1] = __expf(sc[t][1] - mn0);
            sc[t][2] = __expf(sc[t][2] - mn1);
            sc[t][3] = __expf(sc[t][3] - mn1);
            sum0 += sc[t][0] + sc[t][1];
            sum1 += sc[t][2] + sc[t][3];
        }
        sum0 += __shfl_xor_sync(0xffffffffu, sum0, 1);
        sum0 += __shfl_xor_sync(0xffffffffu, sum0, 2);
        sum1 += __shfl_xor_sync(0xffffffffu, sum1, 1);
        sum1 += __shfl_xor_sync(0xffffffffu, sum1, 2);
        l0 = l0 * cr0 + sum0; l1 = l1 * cr1 + sum1;
        m0 = mn0; m1 = mn1;
        #pragma unroll
        for (int t = 0; t < 8; t++) {
            oacc[t][0] *= cr0; oacc[t][1] *= cr0;
            oacc[t][2] *= cr1; oacc[t][3] *= cr1;
        }

        // ---- PV: o += P @ V
        #pragma unroll
        for (int c = 0; c < 4; c++) {
            uint32_t ap[4];
            ap[0] = pack_bf2(sc[2*c][0],   sc[2*c][1]);
            ap[1] = pack_bf2(sc[2*c][2],   sc[2*c][3]);
            ap[2] = pack_bf2(sc[2*c+1][0], sc[2*c+1][1]);
            ap[3] = pack_bf2(sc[2*c+1][2], sc[2*c+1][3]);
            uint32_t bv[8][2];
            #pragma unroll
            for (int nt2 = 0; nt2 < 4; nt2++) {
                uint32_t va = stg + 9216
                    + (c * 16 + (lane & 7) + 8 * ((lane >> 3) & 1)) * AT_RS
                    + (nt2 * 16 + 8 * (lane >> 4)) * 2;
                uint32_t r0, r1, r2, r3;
                LDSM_X4_T(r0, r1, r2, r3, va);
                bv[2*nt2][0] = r0;   bv[2*nt2][1] = r1;
                bv[2*nt2+1][0] = r2; bv[2*nt2+1][1] = r3;
            }
            #pragma unroll
            for (int nt = 0; nt < 8; nt++)
                MMA_BF16(oacc[nt], ap, bv[nt]);
        }
        __syncthreads();
    }

    // ---- epilogue: normalize, emit ctx as bf16
    float inv0 = 1.0f / l0, inv1 = 1.0f / l1;
    const size_t gr0 = (size_t)(b * SS + q0 + wid * 16 + (lane >> 2));
    const size_t gr1 = gr0 + 8;
    #pragma unroll
    for (int nt = 0; nt < 8; nt++) {
        const size_t d = hoff + nt * 8 + (lane & 3) * 2;
        *(uint32_t*)(O + gr0 * DD + d) = pack_bf2(oacc[nt][0] * inv0, oacc[nt][1] * inv0);
        *(uint32_t*)(O + gr1 * DD + d) = pack_bf2(oacc[nt][2] * inv1, oacc[nt][3] * inv1);
    }
}

// ======================= LayerNorm =======================
template<bool EMIT>
__global__ __launch_bounds__(256)
void ln_kernel(const float* __restrict__ X, const float* __restrict__ gw,
               const float* __restrict__ bw, float* __restrict__ Y,
               __nv_bfloat16* __restrict__ Yh, __nv_bfloat16* __restrict__ Yl)
{
    __shared__ float red[2][8];
    const int row = blockIdx.x;
    const int tid = threadIdx.x;
    const float* x = X + (size_t)row * DD;

    float4 v = *(const float4*)(x + tid * 4);
    float s  = v.x + v.y + v.z + v.w;
    float sq = v.x*v.x + v.y*v.y + v.z*v.z + v.w*v.w;
    #pragma unroll
    for (int w = 16; w > 0; w >>= 1) {
        s  += __shfl_xor_sync(0xffffffffu, s,  w);
        sq += __shfl_xor_sync(0xffffffffu, sq, w);
    }
    if ((tid & 31) == 0) { red[0][tid >> 5] = s; red[1][tid >> 5] = sq; }
    __syncthreads();
    float tot = 0.f, totq = 0.f;
    #pragma unroll
    for (int i = 0; i < 8; i++) { tot += red[0][i]; totq += red[1][i]; }

    float mean = tot * (1.0f / DD);
    float var  = totq * (1.0f / DD) - mean * mean;
    float inv  = rsqrtf(var + 1e-12f);

    float4 gg = *(const float4*)(gw + tid * 4);
    float4 bb = *(const float4*)(bw + tid * 4);
    float4 out;
    out.x = (v.x - mean) * inv * gg.x + bb.x;
    out.y = (v.y - mean) * inv * gg.y + bb.y;
    out.z = (v.z - mean) * inv * gg.z + bb.z;
    out.w = (v.w - mean) * inv * gg.w + bb.w;
    *(float4*)(Y + (size_t)row * DD + tid * 4) = out;

    if (EMIT) {
        float hx,lx,hy,ly,hz,lz,hw,lw;
        split1(out.x,hx,lx); split1(out.y,hy,ly);
        split1(out.z,hz,lz); split1(out.w,hw,lw);
        size_t ob = (size_t)row * DD + tid * 4;
        *(uint2*)(Yh + ob) = make_uint2(pack_bf2(hx,hy), pack_bf2(hz,hw));
        *(uint2*)(Yl + ob) = make_uint2(pack_bf2(lx,ly), pack_bf2(lz,lw));
    }
}

// ======================= host launch =======================
extern "C" void kernel_launch(void* const* d_in, const int* in_sizes, int n_in,
                              void* d_out, int out_size)
{
    const float* x    = (const float*)d_in[0];
    const float* mask = (const float*)d_in[1];
    const float* Wq   = (const float*)d_in[2];
    const float* bq   = (const float*)d_in[3];
    const float* Wk   = (const float*)d_in[4];
    const float* bk   = (const float*)d_in[5];
    const float* Wv   = (const float*)d_in[6];
    const float* bv   = (const float*)d_in[7];
    const float* Wo   = (const float*)d_in[8];
    const float* bo   = (const float*)d_in[9];
    const float* ln1g = (const float*)d_in[10];
    const float* ln1b = (const float*)d_in[11];
    const float* Wi   = (const float*)d_in[12];
    const float* bi   = (const float*)d_in[13];
    const float* Wo2  = (const float*)d_in[14];
    const float* bo2  = (const float*)d_in[15];
    const float* ln2g = (const float*)d_in[16];
    const float* ln2b = (const float*)d_in[17];

    float *t1, *att, *t2;
    __nv_bfloat16 *xh, *qh, *kh, *vh, *ct, *ath, *atl, *hh, *hl;
    __nv_bfloat16 *wqh,*wql,*wkh,*wkl,*wvh,*wvl,*woh,*wol,*wih,*wil,*w2h,*w2l;
    cudaGetSymbolAddress((void**)&t1,  g_t1);
    cudaGetSymbolAddress((void**)&att, g_att);
    cudaGetSymbolAddress((void**)&t2,  g_t2);
    cudaGetSymbolAddress((void**)&xh,  g_xh);
    cudaGetSymbolAddress((void**)&qh,  g_qh);
    cudaGetSymbolAddress((void**)&kh,  g_kh);
    cudaGetSymbolAddress((void**)&vh,  g_vh);
    cudaGetSymbolAddress((void**)&ct,  g_ct);
    cudaGetSymbolAddress((void**)&ath, g_ath);
    cudaGetSymbolAddress((void**)&atl, g_atl);
    cudaGetSymbolAddress((void**)&hh,  g_hh);
    cudaGetSymbolAddress((void**)&hl,  g_hl);
    cudaGetSymbolAddress((void**)&wqh, g_wqh); cudaGetSymbolAddress((void**)&wql, g_wql);
    cudaGetSymbolAddress((void**)&wkh, g_wkh); cudaGetSymbolAddress((void**)&wkl, g_wkl);
    cudaGetSymbolAddress((void**)&wvh, g_wvh); cudaGetSymbolAddress((void**)&wvl, g_wvl);
    cudaGetSymbolAddress((void**)&woh, g_woh); cudaGetSymbolAddress((void**)&wol, g_wol);
    cudaGetSymbolAddress((void**)&wih, g_wih); cudaGetSymbolAddress((void**)&wil, g_wil);
    cudaGetSymbolAddress((void**)&w2h, g_w2h); cudaGetSymbolAddress((void**)&w2l, g_w2l);

    const int G1_SMEM = 2 * 20480;         // 40960
    cudaFuncSetAttribute(qkv_gemm,  cudaFuncAttributeMaxDynamicSharedMemorySize, G1_SMEM);
    cudaFuncSetAttribute(oproj_gemm,cudaFuncAttributeMaxDynamicSharedMemorySize, G1_SMEM);
    const int GEMM_SMEM = 2 * STG_BYTES;   // 81920
    cudaFuncSetAttribute(mma_gemm<1>, cudaFuncAttributeMaxDynamicSharedMemorySize, GEMM_SMEM);
    cudaFuncSetAttribute(mma_gemm<2>, cudaFuncAttributeMaxDynamicSharedMemorySize, GEMM_SMEM);
    const int ATTN_SMEM = 2 * AT_STAGE;    // 36864
    cudaFuncSetAttribute(attn_bf16, cudaFuncAttributeMaxDynamicSharedMemorySize, ATTN_SMEM);

    dim3 gQ(DD/128, MTOT/128);       // 8 x 64
    dim3 gQ3(DD/128, MTOT/128, 3);   // fused QKV
    dim3 gF1(DFFN/128, MTOT/128);    // 32 x 64

    // launches 0-2: QKV weight transforms
    wtrans_kernel<<<dim3(DD/32, DD/32), 256>>>(Wq, wqh, wql, DD, DD);
    wtrans_kernel<<<dim3(DD/32, DD/32), 256>>>(Wk, wkh, wkl, DD, DD);
    wtrans_kernel<<<dim3(DD/32, DD/32), 256>>>(Wv, wvh, wvl, DD, DD);
    // launch 3: x -> bf16
    cvt_kernel<<<(MTOT*DD/4 + 255)/256, 256>>>((const float4*)x, (uint2*)xh, MTOT*DD/4);
    // launch 4: fused QKV (Q pre-scaled 1/8)
    qkv_gemm<<<gQ3, 256, G1_SMEM>>>(xh, wqh, wkh, wvh, bq, bk, bv, qh, kh, vh, MTOT, DD, DD);
    // launch 5: attention  (ncu -s 5 profiles this)
    attn_bf16<<<dim3(SS/128, BB*HH), 256, ATTN_SMEM>>>(qh, kh, vh, mask, ct);
    // O projection + residual -> t1; LN1 -> att (+hi/lo)
    wtrans_kernel<<<dim3(DD/32, DD/32), 256>>>(Wo, woh, wol, DD, DD);
    oproj_gemm<<<gQ, 256, G1_SMEM>>>(ct, woh, bo, x, t1, MTOT, DD, DD);
    ln_kernel<true><<<MTOT, 256>>>(t1, ln1g, ln1b, att, ath, atl);
    // FFN (3-product, accuracy-critical)
    wtrans_kernel<<<dim3(DFFN/32, DD/32), 256>>>(Wi, wih, wil, DD, DFFN);
    mma_gemm<2><<<gF1, 256, GEMM_SMEM>>>(ath, atl, wih, wil, bi, nullptr, nullptr, hh, hl, MTOT, DFFN, DD);
    wtrans_kernel<<<dim3(DD/32, DFFN/32), 256>>>(Wo2, w2h, w2l, DFFN, DD);
    mma_gemm<1><<<gF1.y == 0 ? gQ : gQ, 256, GEMM_SMEM>>>(hh, hl, w2h, w2l, bo2, att, t2, nullptr, nullptr, MTOT, DD, DFFN);
    ln_kernel<false><<<MTOT, 256>>>(t2, ln2g, ln2b, (float*)d_out, nullptr, nullptr);
}

// round 7
// speedup vs baseline: 4.6335x; 1.2863x over previous
#include <cuda_runtime.h>
#include <cuda_bf16.h>
#include <math.h>
#include <stdint.h>
#include <stddef.h>

#define BB   4
#define SS   2048
#define DD   1024
#define HH   16
#define HDIM 64
#define DFFN 4096
#define MTOT (BB*SS)   // 8192

// ======================= scratch =======================
__device__ float g_t1  [(size_t)MTOT*DD];
__device__ float g_att [(size_t)MTOT*DD];
__device__ float g_attr[(size_t)MTOT*DD];     // tf32-rounded att
__device__ float g_t2  [(size_t)MTOT*DD];
__device__ float g_h   [(size_t)MTOT*DFFN];   // tf32-rounded gelu output
__device__ __nv_bfloat16 g_xh[(size_t)MTOT*DD];
__device__ __nv_bfloat16 g_qh[(size_t)MTOT*DD];
__device__ __nv_bfloat16 g_kh[(size_t)MTOT*DD];
__device__ __nv_bfloat16 g_vh[(size_t)MTOT*DD];
__device__ __nv_bfloat16 g_ct[(size_t)MTOT*DD];
// transposed weights [N, K]
__device__ __nv_bfloat16 g_wq[(size_t)DD*DD], g_wk[(size_t)DD*DD];
__device__ __nv_bfloat16 g_wv[(size_t)DD*DD], g_wo[(size_t)DD*DD];
__device__ float g_wit[(size_t)DD*DFFN];      // tf32-rounded fp32
__device__ float g_w2t[(size_t)DFFN*DD];

// ======================= helpers =======================
__device__ __forceinline__ uint32_t smem_u32(const void* p) {
    uint32_t a;
    asm("{ .reg .u64 t; cvta.to.shared.u64 t, %1; cvt.u32.u64 %0, t; }" : "=r"(a) : "l"(p));
    return a;
}
__device__ __forceinline__ uint32_t pack_bf2(float a, float b) {
    __nv_bfloat162 t = __floats2bfloat162_rn(a, b);
    return *reinterpret_cast<uint32_t*>(&t);
}
__device__ __forceinline__ uint32_t cvt_tf32(float v) {
    uint32_t u;
    asm("cvt.rna.tf32.f32 %0, %1;" : "=r"(u) : "f"(v));
    return u;
}

#define CP_ASYNC16(dst, src) \
    asm volatile("cp.async.cg.shared.global [%0], [%1], 16;" :: "r"(dst), "l"(src) : "memory")
#define CP_COMMIT() asm volatile("cp.async.commit_group;" ::: "memory")
#define CP_WAIT1()  asm volatile("cp.async.wait_group 1;" ::: "memory")

#define LDSM_X4(r0, r1, r2, r3, addr) \
    asm volatile("ldmatrix.sync.aligned.m8n8.x4.shared.b16 {%0,%1,%2,%3}, [%4];" \
        : "=r"(r0), "=r"(r1), "=r"(r2), "=r"(r3) : "r"(addr))

#define LDSM_X4_T(r0, r1, r2, r3, addr) \
    asm volatile("ldmatrix.sync.aligned.m8n8.x4.trans.shared.b16 {%0,%1,%2,%3}, [%4];" \
        : "=r"(r0), "=r"(r1), "=r"(r2), "=r"(r3) : "r"(addr))

#define MMA_BF16(d, a, b) \
    asm volatile("mma.sync.aligned.m16n8k16.row.col.f32.bf16.bf16.f32 " \
        "{%0,%1,%2,%3}, {%4,%5,%6,%7}, {%8,%9}, {%0,%1,%2,%3};" \
        : "+f"((d)[0]), "+f"((d)[1]), "+f"((d)[2]), "+f"((d)[3]) \
        : "r"((a)[0]), "r"((a)[1]), "r"((a)[2]), "r"((a)[3]), \
          "r"((b)[0]), "r"((b)[1]))

#define MMA_TF32(d, a, b) \
    asm volatile("mma.sync.aligned.m16n8k8.row.col.f32.tf32.tf32.f32 " \
        "{%0,%1,%2,%3}, {%4,%5,%6,%7}, {%8,%9}, {%0,%1,%2,%3};" \
        : "+f"((d)[0]), "+f"((d)[1]), "+f"((d)[2]), "+f"((d)[3]) \
        : "r"((a)[0]), "r"((a)[1]), "r"((a)[2]), "r"((a)[3]), \
          "r"((b)[0]), "r"((b)[1]))

// fp32 -> bf16
__global__ __launch_bounds__(256)
void cvt_kernel(const float4* __restrict__ in, uint2* __restrict__ oh, int n4)
{
    int i = blockIdx.x * 256 + threadIdx.x;
    if (i >= n4) return;
    float4 v = in[i];
    oh[i] = make_uint2(pack_bf2(v.x, v.y), pack_bf2(v.z, v.w));
}

// fused transpose of the 4 attention weights: W [K,N] fp32 -> [N,K] bf16
__global__ __launch_bounds__(256)
void whtrans4(const float* __restrict__ W0, const float* __restrict__ W1,
              const float* __restrict__ W2, const float* __restrict__ W3,
              __nv_bfloat16* __restrict__ T0, __nv_bfloat16* __restrict__ T1,
              __nv_bfloat16* __restrict__ T2, __nv_bfloat16* __restrict__ T3)
{
    __shared__ float tile[32][33];
    const int z = blockIdx.z;
    const float* W = (z == 0) ? W0 : (z == 1) ? W1 : (z == 2) ? W2 : W3;
    __nv_bfloat16* T = (z == 0) ? T0 : (z == 1) ? T1 : (z == 2) ? T2 : T3;
    int n0 = blockIdx.x * 32, k0 = blockIdx.y * 32;
    int tx = threadIdx.x & 31, ty = threadIdx.x >> 5;
    #pragma unroll
    for (int i = ty; i < 32; i += 8)
        tile[i][tx] = W[(size_t)(k0 + i) * DD + n0 + tx];
    __syncthreads();
    #pragma unroll
    for (int i = ty; i < 32; i += 8)
        T[(size_t)(n0 + i) * DD + k0 + tx] = __float2bfloat16_rn(tile[tx][i]);
}

// transpose + tf32-round: W [K,N] fp32 -> T [N,K] fp32(tf32)
__global__ __launch_bounds__(256)
void ftrans_kernel(const float* __restrict__ W, uint32_t* __restrict__ T, int K, int N)
{
    __shared__ float tile[32][33];
    int n0 = blockIdx.x * 32, k0 = blockIdx.y * 32;
    int tx = threadIdx.x & 31, ty = threadIdx.x >> 5;
    #pragma unroll
    for (int i = ty; i < 32; i += 8)
        tile[i][tx] = W[(size_t)(k0 + i) * N + n0 + tx];
    __syncthreads();
    #pragma unroll
    for (int i = ty; i < 32; i += 8)
        T[(size_t)(n0 + i) * K + k0 + tx] = cvt_tf32(tile[tx][i]);
}

// ======================= single-product bf16 GEMM core =======================
// C[M,N] = A[M,K] @ B^T (B stored [N,K]); bf16 operands.
// EPI 1: +bias +res -> fp32 ; EPI 3: (+bias)*scale -> bf16
template<int EPI>
__device__ __forceinline__
void gemm1_core(char* dsm, const __nv_bfloat16* __restrict__ A,
                const __nv_bfloat16* __restrict__ B,
                const float* __restrict__ bias, const float* __restrict__ res,
                float* __restrict__ outF, __nv_bfloat16* __restrict__ outB,
                int M, int N, int K, float oscale)
{
    const int tid = threadIdx.x;
    const int wid = tid >> 5;
    const int lane = tid & 31;
    const int bm = blockIdx.y * 128;
    const int bn = blockIdx.x * 128;
    const int warpM = (wid & 1) * 64;
    const int warpN = (wid >> 1) * 32;
    const uint32_t sbase = smem_u32(dsm);

    float acc[4][4][4];
    #pragma unroll
    for (int mt = 0; mt < 4; mt++)
        #pragma unroll
        for (int nt = 0; nt < 4; nt++)
            #pragma unroll
            for (int r = 0; r < 4; r++) acc[mt][nt][r] = 0.f;

    const int NC = K >> 5;

    {
        #pragma unroll
        for (int t = 0; t < 2; t++) {
            int id = tid + t * 256;
            int row = id >> 2, ch = id & 3;
            uint32_t doff = sbase + row * 80 + ch * 16;
            CP_ASYNC16(doff,         A + (size_t)(bm + row) * K + ch * 8);
            CP_ASYNC16(doff + 10240, B + (size_t)(bn + row) * K + ch * 8);
        }
        CP_COMMIT();
    }

    for (int c = 0; c < NC; c++) {
        const int s = c & 1;
        if (c + 1 < NC) {
            const int k0 = (c + 1) << 5;
            uint32_t sb2 = sbase + (s ^ 1) * 20480;
            #pragma unroll
            for (int t = 0; t < 2; t++) {
                int id = tid + t * 256;
                int row = id >> 2, ch = id & 3;
                uint32_t doff = sb2 + row * 80 + ch * 16;
                CP_ASYNC16(doff,         A + (size_t)(bm + row) * K + k0 + ch * 8);
                CP_ASYNC16(doff + 10240, B + (size_t)(bn + row) * K + k0 + ch * 8);
            }
        }
        CP_COMMIT();
        CP_WAIT1();
        __syncthreads();

        const uint32_t sb = sbase + s * 20480;
        const uint32_t arow = (lane & 15);
        const uint32_t khalf = (lane >> 4);
        #pragma unroll
        for (int ks = 0; ks < 2; ks++) {
            uint32_t ah[4][4], bh[4][2];
            const uint32_t koff = ks * 32 + khalf * 16;
            #pragma unroll
            for (int mt = 0; mt < 4; mt++) {
                uint32_t ra = sb + (warpM + mt * 16 + arow) * 80 + koff;
                LDSM_X4(ah[mt][0], ah[mt][1], ah[mt][2], ah[mt][3], ra);
            }
            #pragma unroll
            for (int g = 0; g < 2; g++) {
                uint32_t rb = sb + 10240 + (warpN + g * 16 + arow) * 80 + koff;
                uint32_t r0, r1, r2, r3;
                LDSM_X4(r0, r1, r2, r3, rb);
                bh[g*2+0][0] = r0; bh[g*2+0][1] = r2;
                bh[g*2+1][0] = r1; bh[g*2+1][1] = r3;
            }
            #pragma unroll
            for (int mt = 0; mt < 4; mt++)
                #pragma unroll
                for (int nt = 0; nt < 4; nt++)
                    MMA_BF16(acc[mt][nt], ah[mt], bh[nt]);
        }
        __syncthreads();
    }

    #pragma unroll
    for (int mt = 0; mt < 4; mt++) {
        #pragma unroll
        for (int nt = 0; nt < 4; nt++) {
            const int row0 = bm + warpM + mt * 16 + (lane >> 2);
            const int col  = bn + warpN + nt * 8 + (lane & 3) * 2;
            float2 bb = *(const float2*)(bias + col);
            float v0 = acc[mt][nt][0] + bb.x;
            float v1 = acc[mt][nt][1] + bb.y;
            float v2 = acc[mt][nt][2] + bb.x;
            float v3 = acc[mt][nt][3] + bb.y;
            if (EPI == 1) {
                float2 r0 = *(const float2*)(res + (size_t)row0 * N + col);
                float2 r1 = *(const float2*)(res + (size_t)(row0 + 8) * N + col);
                v0 += r0.x; v1 += r0.y; v2 += r1.x; v3 += r1.y;
                *(float2*)(outF + (size_t)row0 * N + col)       = make_float2(v0, v1);
                *(float2*)(outF + (size_t)(row0 + 8) * N + col) = make_float2(v2, v3);
            }
            if (EPI == 3) {
                v0 *= oscale; v1 *= oscale; v2 *= oscale; v3 *= oscale;
                *(uint32_t*)(outB + (size_t)row0 * N + col)       = pack_bf2(v0, v1);
                *(uint32_t*)(outB + (size_t)(row0 + 8) * N + col) = pack_bf2(v2, v3);
            }
        }
    }
}

__global__ __launch_bounds__(256, 2)
void qkv_gemm(const __nv_bfloat16* __restrict__ A,
              const __nv_bfloat16* __restrict__ Bq, const __nv_bfloat16* __restrict__ Bk,
              const __nv_bfloat16* __restrict__ Bv,
              const float* __restrict__ bq, const float* __restrict__ bk,
              const float* __restrict__ bv,
              __nv_bfloat16* __restrict__ oq, __nv_bfloat16* __restrict__ ok,
              __nv_bfloat16* __restrict__ ov, int M, int N, int K)
{
    extern __shared__ char dsm[];
    const int z = blockIdx.z;
    const __nv_bfloat16* B = (z == 0) ? Bq : (z == 1) ? Bk : Bv;
    const float* bias      = (z == 0) ? bq : (z == 1) ? bk : bv;
    __nv_bfloat16* out     = (z == 0) ? oq : (z == 1) ? ok : ov;
    float sc               = (z == 0) ? 0.125f : 1.0f;
    gemm1_core<3>(dsm, A, B, bias, nullptr, nullptr, out, M, N, K, sc);
}

__global__ __launch_bounds__(256, 2)
void oproj_gemm(const __nv_bfloat16* __restrict__ A, const __nv_bfloat16* __restrict__ B,
                const float* __restrict__ bias, const float* __restrict__ res,
                float* __restrict__ outF, int M, int N, int K)
{
    extern __shared__ char dsm[];
    gemm1_core<1>(dsm, A, B, bias, res, outF, nullptr, M, N, K, 1.0f);
}

// ======================= tf32 GEMM (FFN) =======================
// C[M,N] = A[M,K] @ B^T (B stored [N,K]); fp32(tf32-rounded) operands.
// EPI 1: +bias+res -> fp32 ; EPI 2: +bias, gelu -> fp32(tf32)
// stage: A@0 (128 rows x 144B = 18432), B@18432; stage stride 36864.
#define FSTG 36864

template<int EPI>
__global__ __launch_bounds__(256, 2)
void ffn_gemm(const float* __restrict__ A, const float* __restrict__ B,
              const float* __restrict__ bias, const float* __restrict__ res,
              float* __restrict__ outF, uint32_t* __restrict__ outT,
              int M, int N, int K)
{
    extern __shared__ char dsm[];
    const int tid = threadIdx.x;
    const int wid = tid >> 5;
    const int lane = tid & 31;
    const int bm = blockIdx.y * 128;
    const int bn = blockIdx.x * 128;
    const int warpM = (wid & 1) * 64;
    const int warpN = (wid >> 1) * 32;
    const uint32_t sbase = smem_u32(dsm);

    float acc[4][4][4];
    #pragma unroll
    for (int mt = 0; mt < 4; mt++)
        #pragma unroll
        for (int nt = 0; nt < 4; nt++)
            #pragma unroll
            for (int r = 0; r < 4; r++) acc[mt][nt][r] = 0.f;

    const int NC = K >> 5;   // BK = 32 fp32

    {
        #pragma unroll
        for (int t = 0; t < 4; t++) {
            int id = tid + t * 256;            // 0..1023: 128 rows x 8 chunks
            int row = id >> 3, ch = id & 7;
            uint32_t doff = sbase + row * 144 + ch * 16;
            CP_ASYNC16(doff,         A + (size_t)(bm + row) * K + ch * 4);
            CP_ASYNC16(doff + 18432, B + (size_t)(bn + row) * K + ch * 4);
        }
        CP_COMMIT();
    }

    for (int c = 0; c < NC; c++) {
        const int s = c & 1;
        if (c + 1 < NC) {
            const int k0 = (c + 1) << 5;
            uint32_t sb2 = sbase + (s ^ 1) * FSTG;
            #pragma unroll
            for (int t = 0; t < 4; t++) {
                int id = tid + t * 256;
                int row = id >> 3, ch = id & 7;
                uint32_t doff = sb2 + row * 144 + ch * 16;
                CP_ASYNC16(doff,         A + (size_t)(bm + row) * K + k0 + ch * 4);
                CP_ASYNC16(doff + 18432, B + (size_t)(bn + row) * K + k0 + ch * 4);
            }
        }
        CP_COMMIT();
        CP_WAIT1();
        __syncthreads();

        const uint32_t sb = sbase + s * FSTG;
        const uint32_t arow = (lane & 15);
        const uint32_t khalf = (lane >> 4);
        #pragma unroll
        for (int k8 = 0; k8 < 4; k8++) {
            uint32_t ah[4][4], bh[4][2];
            const uint32_t koff = k8 * 32 + khalf * 16;
            #pragma unroll
            for (int mt = 0; mt < 4; mt++) {
                uint32_t ra = sb + (warpM + mt * 16 + arow) * 144 + koff;
                LDSM_X4(ah[mt][0], ah[mt][1], ah[mt][2], ah[mt][3], ra);
            }
            #pragma unroll
            for (int g = 0; g < 2; g++) {
                uint32_t rb = sb + 18432 + (warpN + g * 16 + arow) * 144 + koff;
                uint32_t r0, r1, r2, r3;
                LDSM_X4(r0, r1, r2, r3, rb);
                bh[g*2+0][0] = r0; bh[g*2+0][1] = r2;
                bh[g*2+1][0] = r1; bh[g*2+1][1] = r3;
            }
            #pragma unroll
            for (int mt = 0; mt < 4; mt++)
                #pragma unroll
                for (int nt = 0; nt < 4; nt++)
                    MMA_TF32(acc[mt][nt], ah[mt], bh[nt]);
        }
        __syncthreads();
    }

    #pragma unroll
    for (int mt = 0; mt < 4; mt++) {
        #pragma unroll
        for (int nt = 0; nt < 4; nt++) {
            const int row0 = bm + warpM + mt * 16 + (lane >> 2);
            const int col  = bn + warpN + nt * 8 + (lane & 3) * 2;
            float2 bb = *(const float2*)(bias + col);
            float v0 = acc[mt][nt][0] + bb.x;
            float v1 = acc[mt][nt][1] + bb.y;
            float v2 = acc[mt][nt][2] + bb.x;
            float v3 = acc[mt][nt][3] + bb.y;
            if (EPI == 1) {
                float2 r0 = *(const float2*)(res + (size_t)row0 * N + col);
                float2 r1 = *(const float2*)(res + (size_t)(row0 + 8) * N + col);
                v0 += r0.x; v1 += r0.y; v2 += r1.x; v3 += r1.y;
                *(float2*)(outF + (size_t)row0 * N + col)       = make_float2(v0, v1);
                *(float2*)(outF + (size_t)(row0 + 8) * N + col) = make_float2(v2, v3);
            }
            if (EPI == 2) {
                v0 = 0.5f * v0 * (1.0f + erff(v0 * 0.70710678118654752f));
                v1 = 0.5f * v1 * (1.0f + erff(v1 * 0.70710678118654752f));
                v2 = 0.5f * v2 * (1.0f + erff(v2 * 0.70710678118654752f));
                v3 = 0.5f * v3 * (1.0f + erff(v3 * 0.70710678118654752f));
                *(uint2*)(outT + (size_t)row0 * N + col) =
                    make_uint2(cvt_tf32(v0), cvt_tf32(v1));
                *(uint2*)(outT + (size_t)(row0 + 8) * N + col) =
                    make_uint2(cvt_tf32(v2), cvt_tf32(v3));
            }
        }
    }
}

// ======================= bf16 flash attention =======================
#define AT_RS    144
#define AT_STAGE 18432

__global__ __launch_bounds__(256, 2)
void attn_bf16(const __nv_bfloat16* __restrict__ Qh, const __nv_bfloat16* __restrict__ Kh,
               const __nv_bfloat16* __restrict__ Vh, const float* __restrict__ mask,
               __nv_bfloat16* __restrict__ O)
{
    extern __shared__ char asmem[];
    __shared__ float msks[2][64];

    const int tid = threadIdx.x;
    const int wid = tid >> 5;
    const int lane = tid & 31;
    const int b = blockIdx.y >> 4;
    const int h = blockIdx.y & 15;
    const int q0 = blockIdx.x * 128;
    const uint32_t sb = smem_u32(asmem);
    const size_t hoff = (size_t)h * HDIM;

    #pragma unroll
    for (int t = 0; t < 4; t++) {
        int id = tid + t * 256;
        int r = id >> 3, ch = id & 7;
        size_t src = (size_t)(b * SS + q0 + r) * DD + hoff + ch * 8;
        *(uint4*)(asmem + r * AT_RS + ch * 16) = *(const uint4*)(Qh + src);
    }
    __syncthreads();

    uint32_t aq[4][4];
    {
        const uint32_t arow = lane & 15, khalf = lane >> 4;
        #pragma unroll
        for (int c = 0; c < 4; c++) {
            uint32_t ra = sb + (wid * 16 + arow) * AT_RS + c * 32 + khalf * 16;
            LDSM_X4(aq[c][0], aq[c][1], aq[c][2], aq[c][3], ra);
        }
    }
    __syncthreads();

    float oacc[8][4];
    #pragma unroll
    for (int t = 0; t < 8; t++)
        #pragma unroll
        for (int r = 0; r < 4; r++) oacc[t][r] = 0.f;
    float m0 = -INFINITY, m1 = -INFINITY, l0 = 0.f, l1 = 0.f;

    {
        #pragma unroll
        for (int t = 0; t < 2; t++) {
            int id = tid + t * 256;
            int r = id >> 3, ch = id & 7;
            size_t src = (size_t)(b * SS + r) * DD + hoff + ch * 8;
            uint32_t dst = sb + r * AT_RS + ch * 16;
            CP_ASYNC16(dst,        Kh + src);
            CP_ASYNC16(dst + 9216, Vh + src);
        }
        if (tid < 16)
            CP_ASYNC16(smem_u32(&msks[0][0]) + tid * 16, mask + (size_t)b * SS + tid * 4);
        CP_COMMIT();
    }

    const uint32_t arow = lane & 15, khalf = lane >> 4;

    for (int it = 0; it < SS / 64; it++) {
        const int s = it & 1;
        if (it + 1 < SS / 64) {
            const int kt = (it + 1) * 64;
            uint32_t sb2 = sb + (s ^ 1) * AT_STAGE;
            #pragma unroll
            for (int t = 0; t < 2; t++) {
                int id = tid + t * 256;
                int r = id >> 3, ch = id & 7;
                size_t src = (size_t)(b * SS + kt + r) * DD + hoff + ch * 8;
                uint32_t dst = sb2 + r * AT_RS + ch * 16;
                CP_ASYNC16(dst,        Kh + src);
                CP_ASYNC16(dst + 9216, Vh + src);
            }
            if (tid < 16)
                CP_ASYNC16(smem_u32(&msks[s ^ 1][0]) + tid * 16,
                           mask + (size_t)b * SS + kt + tid * 4);
        }
        CP_COMMIT();
        CP_WAIT1();
        __syncthreads();

        const uint32_t stg = sb + s * AT_STAGE;

        float sc[8][4];
        #pragma unroll
        for (int t = 0; t < 8; t++)
            #pragma unroll
            for (int r = 0; r < 4; r++) sc[t][r] = 0.f;

        #pragma unroll
        for (int g = 0; g < 4; g++) {
            #pragma unroll
            for (int c = 0; c < 4; c++) {
                uint32_t rb = stg + (g * 16 + arow) * AT_RS + c * 32 + khalf * 16;
                uint32_t r0, r1, r2, r3, bh0[2], bh1[2];
                LDSM_X4(r0, r1, r2, r3, rb);
                bh0[0] = r0; bh0[1] = r2; bh1[0] = r1; bh1[1] = r3;
                MMA_BF16(sc[2*g],   aq[c], bh0);
                MMA_BF16(sc[2*g+1], aq[c], bh1);
            }
        }

        float mx0 = -INFINITY, mx1 = -INFINITY;
        #pragma unroll
        for (int t = 0; t < 8; t++) {
            float mk0 = msks[s][t * 8 + (lane & 3) * 2];
            float mk1 = msks[s][t * 8 + (lane & 3) * 2 + 1];
            sc[t][0] += mk0; sc[t][1] += mk1;
            sc[t][2] += mk0; sc[t][3] += mk1;
            mx0 = fmaxf(mx0, fmaxf(sc[t][0], sc[t][1]));
            mx1 = fmaxf(mx1, fmaxf(sc[t][2], sc[t][3]));
        }
        mx0 = fmaxf(mx0, __shfl_xor_sync(0xffffffffu, mx0, 1));
        mx0 = fmaxf(mx0, __shfl_xor_sync(0xffffffffu, mx0, 2));
        mx1 = fmaxf(mx1, __shfl_xor_sync(0xffffffffu, mx1, 1));
        mx1 = fmaxf(mx1, __shfl_xor_sync(0xffffffffu, mx1, 2));
        float mn0 = fmaxf(m0, mx0), mn1 = fmaxf(m1, mx1);
        float cr0 = __expf(m0 - mn0), cr1 = __expf(m1 - mn1);
        float sum0 = 0.f, sum1 = 0.f;
        #pragma unroll
        for (int t = 0; t < 8; t++) {
            sc[t][0] = __expf(sc[t][0] - mn0);
            sc[t][1] = __expf(sc[t][1] - mn0);
            sc[t][2] = __expf(sc[t][2] - mn1);
            sc[t][3] = __expf(sc[t][3] - mn1);
            sum0 += sc[t][0] + sc[t][1];
            sum1 += sc[t][2] + sc[t][3];
        }
        sum0 += __shfl_xor_sync(0xffffffffu, sum0, 1);
        sum0 += __shfl_xor_sync(0xffffffffu, sum0, 2);
        sum1 += __shfl_xor_sync(0xffffffffu, sum1, 1);
        sum1 += __shfl_xor_sync(0xffffffffu, sum1, 2);
        l0 = l0 * cr0 + sum0; l1 = l1 * cr1 + sum1;
        m0 = mn0; m1 = mn1;
        #pragma unroll
        for (int t = 0; t < 8; t++) {
            oacc[t][0] *= cr0; oacc[t][1] *= cr0;
            oacc[t][2] *= cr1; oacc[t][3] *= cr1;
        }

        #pragma unroll
        for (int c = 0; c < 4; c++) {
            uint32_t ap[4];
            ap[0] = pack_bf2(sc[2*c][0],   sc[2*c][1]);
            ap[1] = pack_bf2(sc[2*c][2],   sc[2*c][3]);
            ap[2] = pack_bf2(sc[2*c+1][0], sc[2*c+1][1]);
            ap[3] = pack_bf2(sc[2*c+1][2], sc[2*c+1][3]);
            uint32_t bv[8][2];
            #pragma unroll
            for (int nt2 = 0; nt2 < 4; nt2++) {
                uint32_t va = stg + 9216
                    + (c * 16 + (lane & 7) + 8 * ((lane >> 3) & 1)) * AT_RS
                    + (nt2 * 16 + 8 * (lane >> 4)) * 2;
                uint32_t r0, r1, r2, r3;
                LDSM_X4_T(r0, r1, r2, r3, va);
                bv[2*nt2][0] = r0;   bv[2*nt2][1] = r1;
                bv[2*nt2+1][0] = r2; bv[2*nt2+1][1] = r3;
            }
            #pragma unroll
            for (int nt = 0; nt < 8; nt++)
                MMA_BF16(oacc[nt], ap, bv[nt]);
        }
        __syncthreads();
    }

    float inv0 = 1.0f / l0, inv1 = 1.0f / l1;
    const size_t gr0 = (size_t)(b * SS + q0 + wid * 16 + (lane >> 2));
    const size_t gr1 = gr0 + 8;
    #pragma unroll
    for (int nt = 0; nt < 8; nt++) {
        const size_t d = hoff + nt * 8 + (lane & 3) * 2;
        *(uint32_t*)(O + gr0 * DD + d) = pack_bf2(oacc[nt][0] * inv0, oacc[nt][1] * inv0);
        *(uint32_t*)(O + gr1 * DD + d) = pack_bf2(oacc[nt][2] * inv1, oacc[nt][3] * inv1);
    }
}

// ======================= LayerNorm =======================
// EMIT_R: additionally emit tf32-rounded copy for the FFN1 A operand
template<bool EMIT_R>
__global__ __launch_bounds__(256)
void ln_kernel(const float* __restrict__ X, const float* __restrict__ gw,
               const float* __restrict__ bw, float* __restrict__ Y,
               uint32_t* __restrict__ Yr)
{
    __shared__ float red[2][8];
    const int row = blockIdx.x;
    const int tid = threadIdx.x;
    const float* x = X + (size_t)row * DD;

    float4 v = *(const float4*)(x + tid * 4);
    float s  = v.x + v.y + v.z + v.w;
    float sq = v.x*v.x + v.y*v.y + v.z*v.z + v.w*v.w;
    #pragma unroll
    for (int w = 16; w > 0; w >>= 1) {
        s  += __shfl_xor_sync(0xffffffffu, s,  w);
        sq += __shfl_xor_sync(0xffffffffu, sq, w);
    }
    if ((tid & 31) == 0) { red[0][tid >> 5] = s; red[1][tid >> 5] = sq; }
    __syncthreads();
    float tot = 0.f, totq = 0.f;
    #pragma unroll
    for (int i = 0; i < 8; i++) { tot += red[0][i]; totq += red[1][i]; }

    float mean = tot * (1.0f / DD);
    float var  = totq * (1.0f / DD) - mean * mean;
    float inv  = rsqrtf(var + 1e-12f);

    float4 gg = *(const float4*)(gw + tid * 4);
    float4 bb = *(const float4*)(bw + tid * 4);
    float4 out;
    out.x = (v.x - mean) * inv * gg.x + bb.x;
    out.y = (v.y - mean) * inv * gg.y + bb.y;
    out.z = (v.z - mean) * inv * gg.z + bb.z;
    out.w = (v.w - mean) * inv * gg.w + bb.w;
    *(float4*)(Y + (size_t)row * DD + tid * 4) = out;

    if (EMIT_R) {
        *(uint4*)(Yr + (size_t)row * DD + tid * 4) =
            make_uint4(cvt_tf32(out.x), cvt_tf32(out.y),
                       cvt_tf32(out.z), cvt_tf32(out.w));
    }
}

// ======================= host launch =======================
extern "C" void kernel_launch(void* const* d_in, const int* in_sizes, int n_in,
                              void* d_out, int out_size)
{
    const float* x    = (const float*)d_in[0];
    const float* mask = (const float*)d_in[1];
    const float* Wq   = (const float*)d_in[2];
    const float* bq   = (const float*)d_in[3];
    const float* Wk   = (const float*)d_in[4];
    const float* bk   = (const float*)d_in[5];
    const float* Wv   = (const float*)d_in[6];
    const float* bv   = (const float*)d_in[7];
    const float* Wo   = (const float*)d_in[8];
    const float* bo   = (const float*)d_in[9];
    const float* ln1g = (const float*)d_in[10];
    const float* ln1b = (const float*)d_in[11];
    const float* Wi   = (const float*)d_in[12];
    const float* bi   = (const float*)d_in[13];
    const float* Wo2  = (const float*)d_in[14];
    const float* bo2  = (const float*)d_in[15];
    const float* ln2g = (const float*)d_in[16];
    const float* ln2b = (const float*)d_in[17];

    float *t1, *att, *attr, *t2, *hbuf, *wit, *w2t;
    __nv_bfloat16 *xh, *qh, *kh, *vh, *ct, *wq, *wk, *wv, *wo;
    cudaGetSymbolAddress((void**)&t1,   g_t1);
    cudaGetSymbolAddress((void**)&att,  g_att);
    cudaGetSymbolAddress((void**)&attr, g_attr);
    cudaGetSymbolAddress((void**)&t2,   g_t2);
    cudaGetSymbolAddress((void**)&hbuf, g_h);
    cudaGetSymbolAddress((void**)&wit,  g_wit);
    cudaGetSymbolAddress((void**)&w2t,  g_w2t);
    cudaGetSymbolAddress((void**)&xh,   g_xh);
    cudaGetSymbolAddress((void**)&qh,   g_qh);
    cudaGetSymbolAddress((void**)&kh,   g_kh);
    cudaGetSymbolAddress((void**)&vh,   g_vh);
    cudaGetSymbolAddress((void**)&ct,   g_ct);
    cudaGetSymbolAddress((void**)&wq,   g_wq);
    cudaGetSymbolAddress((void**)&wk,   g_wk);
    cudaGetSymbolAddress((void**)&wv,   g_wv);
    cudaGetSymbolAddress((void**)&wo,   g_wo);

    const int G1_SMEM = 2 * 20480;
    cudaFuncSetAttribute(qkv_gemm,  cudaFuncAttributeMaxDynamicSharedMemorySize, G1_SMEM);
    cudaFuncSetAttribute(oproj_gemm,cudaFuncAttributeMaxDynamicSharedMemorySize, G1_SMEM);
    const int FF_SMEM = 2 * FSTG;          // 73728
    cudaFuncSetAttribute(ffn_gemm<1>, cudaFuncAttributeMaxDynamicSharedMemorySize, FF_SMEM);
    cudaFuncSetAttribute(ffn_gemm<2>, cudaFuncAttributeMaxDynamicSharedMemorySize, FF_SMEM);
    const int ATTN_SMEM = 2 * AT_STAGE;    // 36864
    cudaFuncSetAttribute(attn_bf16, cudaFuncAttributeMaxDynamicSharedMemorySize, ATTN_SMEM);

    dim3 gQ(DD/128, MTOT/128);       // 8 x 64
    dim3 gQ3(DD/128, MTOT/128, 3);
    dim3 gF1(DFFN/128, MTOT/128);    // 32 x 64

    // 0: all four attention-weight transposes (bf16)
    whtrans4<<<dim3(32, 32, 4), 256>>>(Wq, Wk, Wv, Wo, wq, wk, wv, wo);
    // 1: x -> bf16
    cvt_kernel<<<(MTOT*DD/4 + 255)/256, 256>>>((const float4*)x, (uint2*)xh, MTOT*DD/4);
    // 2: fused QKV (Q pre-scaled 1/8)
    qkv_gemm<<<gQ3, 256, G1_SMEM>>>(xh, wq, wk, wv, bq, bk, bv, qh, kh, vh, MTOT, DD, DD);
    // 3: attention  (ncu captures this: harness offset 2 + index 3 = -s 5)
    attn_bf16<<<dim3(SS/128, BB*HH), 256, ATTN_SMEM>>>(qh, kh, vh, mask, ct);
    // 4: O projection + residual
    oproj_gemm<<<gQ, 256, G1_SMEM>>>(ct, wo, bo, x, t1, MTOT, DD, DD);
    // 5: LN1 -> att (fp32) + attr (tf32)
    ln_kernel<true><<<MTOT, 256>>>(t1, ln1g, ln1b, att, (uint32_t*)attr);
    // 6-9: FFN in tf32
    ftrans_kernel<<<dim3(DFFN/32, DD/32), 256>>>(Wi, (uint32_t*)wit, DD, DFFN);
    ffn_gemm<2><<<gF1, 256, FF_SMEM>>>(attr, wit, bi, nullptr, nullptr, (uint32_t*)hbuf, MTOT, DFFN, DD);
    ftrans_kernel<<<dim3(DD/32, DFFN/32), 256>>>(Wo2, (uint32_t*)w2t, DFFN, DD);
    ffn_gemm<1><<<gQ, 256, FF_SMEM>>>(hbuf, w2t, bo2, att, t2, nullptr, MTOT, DD, DFFN);
    // 10: LN2 -> d_out
    ln_kernel<false><<<MTOT, 256>>>(t2, ln2g, ln2b, (float*)d_out, nullptr);
}